// round 1
// baseline (speedup 1.0000x reference)
#include <cuda_runtime.h>
#include <cuda_bf16.h>

// ---------------- problem constants ----------------
#define NB_MAX   2048
#define C1_IMG   (3*84*84)     // 21168 floats per image
#define C1_WT    (32*3*8*8)    // 6144
#define C1_OUT   (32*20*20)    // 12800 per image
#define C2_IN    C1_OUT
#define C2_OUT   (64*9*9)      // 5184
#define C3_IN    C2_OUT
#define C3_OUT   (64*7*7)      // 3136
#define NE       8
#define NA       6
#define TB       32            // samples per MLP block
#define DC       224           // D-chunk for layer1 (3136 = 14*224)

// ---------------- scratch (device globals; no allocs allowed) ----------------
__device__ float g_x1[(size_t)NB_MAX * C1_OUT];   // ~105 MB
__device__ float g_x2[(size_t)NB_MAX * C2_OUT];   // ~42 MB
__device__ float g_x3[(size_t)NB_MAX * C3_OUT];   // ~26 MB
__device__ int   g_cnt[NE];
__device__ int   g_idx[NE * NB_MAX];

// ---------------- expert bucketing (+ int64/int32 detection) ----------------
__global__ void assign_kernel(const int* __restrict__ rm32, int n) {
    __shared__ int s_is64;
    int tid = threadIdx.x;
    if (tid == 0) s_is64 = 1;
    __syncthreads();
    // If the data is int32, odd 32-bit words are real rm values (0..7, random);
    // probability all 256 sampled odd words are zero is ~0. If int64, high words are 0.
    for (int i = tid; i < 256; i += blockDim.x)
        if (rm32[2*i + 1] != 0) atomicExch(&s_is64, 0);
    if (tid < NE) g_cnt[tid] = 0;
    __syncthreads();
    int is64 = s_is64;
    const long long* rm64 = (const long long*)rm32;
    for (int b = tid; b < n; b += blockDim.x) {
        int e = is64 ? (int)rm64[b] : rm32[b];
        int pos = atomicAdd(&g_cnt[e], 1);
        g_idx[e * NB_MAX + pos] = b;
    }
}

// ---------------- conv1: 3->32, 8x8 s4, 84x84 -> 20x20 ----------------
__global__ void __launch_bounds__(256) conv1_kernel(
    const float* __restrict__ state, const float* __restrict__ k1,
    const float* __restrict__ c1) {
    extern __shared__ float sm[];
    float* img = sm;            // [3][84][84]
    float* wt  = sm + C1_IMG;   // [32][3][8][8]
    int b = blockIdx.x, tid = threadIdx.x;
    const float* src = state + (size_t)b * C1_IMG;   // NHWC
    for (int i = tid; i < C1_IMG; i += 256) {
        int c = i % 3, hw = i / 3;
        img[c * 7056 + hw] = src[i];
    }
    for (int i = tid; i < C1_WT; i += 256) wt[i] = k1[i];
    __syncthreads();

    for (int item = tid; item < 8 * 400; item += 256) {
        int ob = (item / 400) * 4;
        int p  = item % 400;
        int oh = p / 20, ow = p % 20;
        float a0 = c1[ob], a1 = c1[ob+1], a2 = c1[ob+2], a3 = c1[ob+3];
        #pragma unroll
        for (int c = 0; c < 3; ++c) {
            const float* ibase = img + c * 7056 + (oh * 4) * 84 + ow * 4; // 16B aligned
            const float* w0 = wt + ob * 192 + c * 64;
            const float* w1 = w0 + 192;
            const float* w2 = w1 + 192;
            const float* w3 = w2 + 192;
            #pragma unroll
            for (int kh = 0; kh < 8; ++kh) {
                float4 v0 = *(const float4*)(ibase + kh * 84);
                float4 v1 = *(const float4*)(ibase + kh * 84 + 4);
                float vv[8] = {v0.x, v0.y, v0.z, v0.w, v1.x, v1.y, v1.z, v1.w};
                #pragma unroll
                for (int kw = 0; kw < 8; ++kw) {
                    float v = vv[kw];
                    int o = kh * 8 + kw;
                    a0 = fmaf(v, w0[o], a0);
                    a1 = fmaf(v, w1[o], a1);
                    a2 = fmaf(v, w2[o], a2);
                    a3 = fmaf(v, w3[o], a3);
                }
            }
        }
        float* dst = g_x1 + (size_t)b * C1_OUT + ob * 400 + p;
        dst[0]    = fmaxf(a0, 0.f);
        dst[400]  = fmaxf(a1, 0.f);
        dst[800]  = fmaxf(a2, 0.f);
        dst[1200] = fmaxf(a3, 0.f);
    }
}

// ---------------- conv2: 32->64, 4x4 s2, 20x20 -> 9x9 ----------------
__global__ void __launch_bounds__(256) conv2_kernel(
    const float* __restrict__ k2, const float* __restrict__ c2) {
    extern __shared__ float img[];   // [32][20][20]
    int b = blockIdx.x, tid = threadIdx.x;
    const float* src = g_x1 + (size_t)b * C2_IN;
    for (int i = tid; i < C2_IN; i += 256) img[i] = src[i];
    __syncthreads();

    for (int item = tid; item < 16 * 81; item += 256) {
        int ob = (item / 81) * 4;
        int p  = item % 81;
        int oh = p / 9, ow = p % 9;
        float a0 = c2[ob], a1 = c2[ob+1], a2 = c2[ob+2], a3 = c2[ob+3];
        for (int c = 0; c < 32; ++c) {
            const float* ibase = img + c * 400 + (oh * 2) * 20 + ow * 2;
            const float* wb = k2 + (size_t)(ob * 32 + c) * 16;  // +512 per oc
            #pragma unroll
            for (int kh = 0; kh < 4; ++kh) {
                const float* row = ibase + kh * 20;
                float v0 = row[0], v1 = row[1], v2 = row[2], v3 = row[3];
                float4 q0 = *(const float4*)(wb + kh * 4);
                float4 q1 = *(const float4*)(wb + 512 + kh * 4);
                float4 q2 = *(const float4*)(wb + 1024 + kh * 4);
                float4 q3 = *(const float4*)(wb + 1536 + kh * 4);
                a0 = fmaf(v0,q0.x, fmaf(v1,q0.y, fmaf(v2,q0.z, fmaf(v3,q0.w, a0))));
                a1 = fmaf(v0,q1.x, fmaf(v1,q1.y, fmaf(v2,q1.z, fmaf(v3,q1.w, a1))));
                a2 = fmaf(v0,q2.x, fmaf(v1,q2.y, fmaf(v2,q2.z, fmaf(v3,q2.w, a2))));
                a3 = fmaf(v0,q3.x, fmaf(v1,q3.y, fmaf(v2,q3.z, fmaf(v3,q3.w, a3))));
            }
        }
        float* dst = g_x2 + (size_t)b * C2_OUT + ob * 81 + p;
        dst[0]   = fmaxf(a0, 0.f);
        dst[81]  = fmaxf(a1, 0.f);
        dst[162] = fmaxf(a2, 0.f);
        dst[243] = fmaxf(a3, 0.f);
    }
}

// ---------------- conv3: 64->64, 3x3 s1, 9x9 -> 7x7 ----------------
__global__ void __launch_bounds__(256) conv3_kernel(
    const float* __restrict__ k3, const float* __restrict__ c3) {
    extern __shared__ float img[];   // [64][9][9]
    int b = blockIdx.x, tid = threadIdx.x;
    const float* src = g_x2 + (size_t)b * C3_IN;
    for (int i = tid; i < C3_IN; i += 256) img[i] = src[i];
    __syncthreads();

    for (int item = tid; item < 16 * 49; item += 256) {
        int ob = (item / 49) * 4;
        int p  = item % 49;
        int oh = p / 7, ow = p % 7;
        float a0 = c3[ob], a1 = c3[ob+1], a2 = c3[ob+2], a3 = c3[ob+3];
        for (int c = 0; c < 64; ++c) {
            const float* ibase = img + c * 81 + oh * 9 + ow;
            const float* wb = k3 + (size_t)(ob * 64 + c) * 9;   // +576 per oc
            #pragma unroll
            for (int kh = 0; kh < 3; ++kh) {
                float v0 = ibase[kh * 9], v1 = ibase[kh * 9 + 1], v2 = ibase[kh * 9 + 2];
                const float* w0 = wb + kh * 3;
                a0 = fmaf(v0,w0[0],      fmaf(v1,w0[1],      fmaf(v2,w0[2],      a0)));
                a1 = fmaf(v0,w0[576],    fmaf(v1,w0[577],    fmaf(v2,w0[578],    a1)));
                a2 = fmaf(v0,w0[1152],   fmaf(v1,w0[1153],   fmaf(v2,w0[1154],   a2)));
                a3 = fmaf(v0,w0[1728],   fmaf(v1,w0[1729],   fmaf(v2,w0[1730],   a3)));
            }
        }
        float* dst = g_x3 + (size_t)b * C3_OUT + ob * 49 + p;
        dst[0]   = fmaxf(a0, 0.f);
        dst[49]  = fmaxf(a1, 0.f);
        dst[98]  = fmaxf(a2, 0.f);
        dst[147] = fmaxf(a3, 0.f);
    }
}

// ---------------- per-expert MLP (only assigned expert per sample) ----------------
__global__ void __launch_bounds__(64) mlp_kernel(
    const float* __restrict__ W1, const float* __restrict__ B1,
    const float* __restrict__ W2, const float* __restrict__ B2,
    const float* __restrict__ W3, const float* __restrict__ B3,
    const float* __restrict__ W4, const float* __restrict__ B4,
    const float* __restrict__ W5, const float* __restrict__ B5,
    const float* __restrict__ W6, const float* __restrict__ B6,
    float* __restrict__ out) {
    int e = blockIdx.x;
    int base = blockIdx.y * TB;
    int n = g_cnt[e] - base;
    if (n <= 0) return;
    if (n > TB) n = TB;

    __shared__ float tile[TB * DC];      // 28 KB
    __shared__ float hA[TB * 64], hB[TB * 64];
    __shared__ int   sid[TB];
    int j = threadIdx.x;                 // 64 threads = 64 hidden units

    if (j < TB) sid[j] = (j < n) ? g_idx[e * NB_MAX + base + j] : -1;
    __syncthreads();

    // ---- layer 1: [n,3136] @ W1[e] ----
    const float* W1e = W1 + (size_t)e * 3136 * 64;
    float acc[TB];
    #pragma unroll
    for (int s = 0; s < TB; ++s) acc[s] = 0.f;

    for (int dc = 0; dc < 3136; dc += DC) {
        __syncthreads();
        for (int i = j; i < TB * DC; i += 64) {
            int s = i / DC, d = i % DC;
            int bb = sid[s];
            tile[i] = (bb >= 0) ? g_x3[(size_t)bb * C3_OUT + dc + d] : 0.f;
        }
        __syncthreads();
        for (int d = 0; d < DC; d += 4) {
            float w0 = W1e[(size_t)(dc + d    ) * 64 + j];
            float w1 = W1e[(size_t)(dc + d + 1) * 64 + j];
            float w2 = W1e[(size_t)(dc + d + 2) * 64 + j];
            float w3 = W1e[(size_t)(dc + d + 3) * 64 + j];
            #pragma unroll
            for (int s = 0; s < TB; ++s) {
                float4 t = *(const float4*)(tile + s * DC + d);
                acc[s] = fmaf(t.x,w0, fmaf(t.y,w1, fmaf(t.z,w2, fmaf(t.w,w3, acc[s]))));
            }
        }
    }
    float b1 = B1[e * 64 + j];
    #pragma unroll
    for (int s = 0; s < TB; ++s) hA[s * 64 + j] = fmaxf(acc[s] + b1, 0.f);
    __syncthreads();

    // ---- layers 2..5: 64x64 ----
    const float* Ws[4] = {W2, W3, W4, W5};
    const float* Bs[4] = {B2, B3, B4, B5};
    float* hin = hA;
    float* hout = hB;
    for (int L = 0; L < 4; ++L) {
        const float* W = Ws[L] + (size_t)e * 4096;
        float bb = Bs[L][e * 64 + j];
        float a2[TB];
        #pragma unroll
        for (int s = 0; s < TB; ++s) a2[s] = bb;
        for (int k = 0; k < 64; ++k) {
            float w = W[k * 64 + j];
            #pragma unroll
            for (int s = 0; s < TB; ++s)
                a2[s] = fmaf(hin[s * 64 + k], w, a2[s]);
        }
        #pragma unroll
        for (int s = 0; s < TB; ++s) hout[s * 64 + j] = fmaxf(a2[s], 0.f);
        __syncthreads();
        float* t = hin; hin = hout; hout = t;
    }

    // ---- layer 6: 64 -> 6, no relu ----
    if (j < NA) {
        const float* W6e = W6 + (size_t)e * 64 * NA;
        float b6 = B6[e * NA + j];
        for (int s = 0; s < n; ++s) {
            float a = b6;
            #pragma unroll
            for (int k = 0; k < 64; ++k)
                a = fmaf(hin[s * 64 + k], W6e[k * NA + j], a);
            out[(size_t)sid[s] * NA + j] = a;
        }
    }
}

// ---------------- launch ----------------
extern "C" void kernel_launch(void* const* d_in, const int* in_sizes, int n_in,
                              void* d_out, int out_size) {
    const float* state = (const float*)d_in[0];
    const int*   rm    = (const int*)d_in[1];
    const float* k1 = (const float*)d_in[2];
    const float* c1 = (const float*)d_in[3];
    const float* k2 = (const float*)d_in[4];
    const float* c2 = (const float*)d_in[5];
    const float* k3 = (const float*)d_in[6];
    const float* c3 = (const float*)d_in[7];
    const float* W1 = (const float*)d_in[8];
    const float* B1 = (const float*)d_in[9];
    const float* W2 = (const float*)d_in[10];
    const float* B2 = (const float*)d_in[11];
    const float* W3 = (const float*)d_in[12];
    const float* B3 = (const float*)d_in[13];
    const float* W4 = (const float*)d_in[14];
    const float* B4 = (const float*)d_in[15];
    const float* W5 = (const float*)d_in[16];
    const float* B5 = (const float*)d_in[17];
    const float* W6 = (const float*)d_in[18];
    const float* B6 = (const float*)d_in[19];
    float* out = (float*)d_out;

    int nB = in_sizes[1];
    if (nB > NB_MAX) nB = NB_MAX;

    // conv1 needs 109 KB, conv2 51 KB dynamic smem (set every call; deterministic)
    cudaFuncSetAttribute(conv1_kernel, cudaFuncAttributeMaxDynamicSharedMemorySize,
                         (C1_IMG + C1_WT) * 4);
    cudaFuncSetAttribute(conv2_kernel, cudaFuncAttributeMaxDynamicSharedMemorySize,
                         C2_IN * 4);

    assign_kernel<<<1, 256>>>(rm, nB);
    conv1_kernel<<<nB, 256, (C1_IMG + C1_WT) * 4>>>(state, k1, c1);
    conv2_kernel<<<nB, 256, C2_IN * 4>>>(k2, c2);
    conv3_kernel<<<nB, 256, C3_IN * 4>>>(k3, c3);
    mlp_kernel<<<dim3(NE, (nB + TB - 1) / TB), 64>>>(
        W1, B1, W2, B2, W3, B3, W4, B4, W5, B5, W6, B6, out);
}

// round 2
// speedup vs baseline: 1.0020x; 1.0020x over previous
#include <cuda_runtime.h>
#include <cuda_bf16.h>

// ---------------- problem constants ----------------
#define NB_MAX   2048
#define C1_IMG   (3*84*84)     // 21168 floats per image
#define C1_WT    (32*3*8*8)    // 6144
#define C1_OUT   (32*20*20)    // 12800 per image
#define C2_IN    C1_OUT
#define C2_OUT   (64*9*9)      // 5184
#define C3_IN    C2_OUT
#define C3_OUT   (64*7*7)      // 3136
#define NE       8
#define NA       6
#define TB       32            // samples per MLP block
#define DC       224           // D-chunk for layer1 (3136 = 14*224)

// ---------------- scratch (device globals; no allocs allowed) ----------------
__device__ float g_x1[(size_t)NB_MAX * C1_OUT];   // ~105 MB
__device__ float g_x2[(size_t)NB_MAX * C2_OUT];   // ~42 MB
__device__ float g_x3[(size_t)NB_MAX * C3_OUT];   // ~26 MB
__device__ int   g_cnt[NE];
__device__ int   g_idx[NE * NB_MAX];

// ---------------- expert bucketing (+ int64/int32 detection) ----------------
__global__ void assign_kernel(const int* __restrict__ rm32, int n) {
    __shared__ int s_is64;
    int tid = threadIdx.x;
    if (tid == 0) s_is64 = 1;
    __syncthreads();
    // If the data is int32, odd 32-bit words are real rm values (0..7, random);
    // probability all 256 sampled odd words are zero is ~0. If int64, high words are 0.
    for (int i = tid; i < 256; i += blockDim.x)
        if (rm32[2*i + 1] != 0) atomicExch(&s_is64, 0);
    if (tid < NE) g_cnt[tid] = 0;
    __syncthreads();
    int is64 = s_is64;
    const long long* rm64 = (const long long*)rm32;
    for (int b = tid; b < n; b += blockDim.x) {
        int e = is64 ? (int)rm64[b] : rm32[b];
        int pos = atomicAdd(&g_cnt[e], 1);
        g_idx[e * NB_MAX + pos] = b;
    }
}

// ---------------- conv1: 3->32, 8x8 s4, 84x84 -> 20x20 ----------------
__global__ void __launch_bounds__(256) conv1_kernel(
    const float* __restrict__ state, const float* __restrict__ k1,
    const float* __restrict__ c1) {
    extern __shared__ float sm[];
    float* img = sm;            // [3][84][84]
    float* wt  = sm + C1_IMG;   // [32][3][8][8]
    int b = blockIdx.x, tid = threadIdx.x;
    const float* src = state + (size_t)b * C1_IMG;   // NHWC
    for (int i = tid; i < C1_IMG; i += 256) {
        int c = i % 3, hw = i / 3;
        img[c * 7056 + hw] = src[i];
    }
    for (int i = tid; i < C1_WT; i += 256) wt[i] = k1[i];
    __syncthreads();

    for (int item = tid; item < 8 * 400; item += 256) {
        int ob = (item / 400) * 4;
        int p  = item % 400;
        int oh = p / 20, ow = p % 20;
        float a0 = c1[ob], a1 = c1[ob+1], a2 = c1[ob+2], a3 = c1[ob+3];
        #pragma unroll
        for (int c = 0; c < 3; ++c) {
            const float* ibase = img + c * 7056 + (oh * 4) * 84 + ow * 4; // 16B aligned
            const float* w0 = wt + ob * 192 + c * 64;
            const float* w1 = w0 + 192;
            const float* w2 = w1 + 192;
            const float* w3 = w2 + 192;
            #pragma unroll
            for (int kh = 0; kh < 8; ++kh) {
                float4 v0 = *(const float4*)(ibase + kh * 84);
                float4 v1 = *(const float4*)(ibase + kh * 84 + 4);
                float vv[8] = {v0.x, v0.y, v0.z, v0.w, v1.x, v1.y, v1.z, v1.w};
                #pragma unroll
                for (int kw = 0; kw < 8; ++kw) {
                    float v = vv[kw];
                    int o = kh * 8 + kw;
                    a0 = fmaf(v, w0[o], a0);
                    a1 = fmaf(v, w1[o], a1);
                    a2 = fmaf(v, w2[o], a2);
                    a3 = fmaf(v, w3[o], a3);
                }
            }
        }
        float* dst = g_x1 + (size_t)b * C1_OUT + ob * 400 + p;
        dst[0]    = fmaxf(a0, 0.f);
        dst[400]  = fmaxf(a1, 0.f);
        dst[800]  = fmaxf(a2, 0.f);
        dst[1200] = fmaxf(a3, 0.f);
    }
}

// ---------------- conv2: 32->64, 4x4 s2, 20x20 -> 9x9 ----------------
__global__ void __launch_bounds__(256) conv2_kernel(
    const float* __restrict__ k2, const float* __restrict__ c2) {
    extern __shared__ float img[];   // [32][20][20]
    int b = blockIdx.x, tid = threadIdx.x;
    const float* src = g_x1 + (size_t)b * C2_IN;
    for (int i = tid; i < C2_IN; i += 256) img[i] = src[i];
    __syncthreads();

    for (int item = tid; item < 16 * 81; item += 256) {
        int ob = (item / 81) * 4;
        int p  = item % 81;
        int oh = p / 9, ow = p % 9;
        float a0 = c2[ob], a1 = c2[ob+1], a2 = c2[ob+2], a3 = c2[ob+3];
        for (int c = 0; c < 32; ++c) {
            const float* ibase = img + c * 400 + (oh * 2) * 20 + ow * 2;
            const float* wb = k2 + (size_t)(ob * 32 + c) * 16;  // +512 per oc
            #pragma unroll
            for (int kh = 0; kh < 4; ++kh) {
                const float* row = ibase + kh * 20;
                float v0 = row[0], v1 = row[1], v2 = row[2], v3 = row[3];
                float4 q0 = *(const float4*)(wb + kh * 4);
                float4 q1 = *(const float4*)(wb + 512 + kh * 4);
                float4 q2 = *(const float4*)(wb + 1024 + kh * 4);
                float4 q3 = *(const float4*)(wb + 1536 + kh * 4);
                a0 = fmaf(v0,q0.x, fmaf(v1,q0.y, fmaf(v2,q0.z, fmaf(v3,q0.w, a0))));
                a1 = fmaf(v0,q1.x, fmaf(v1,q1.y, fmaf(v2,q1.z, fmaf(v3,q1.w, a1))));
                a2 = fmaf(v0,q2.x, fmaf(v1,q2.y, fmaf(v2,q2.z, fmaf(v3,q2.w, a2))));
                a3 = fmaf(v0,q3.x, fmaf(v1,q3.y, fmaf(v2,q3.z, fmaf(v3,q3.w, a3))));
            }
        }
        float* dst = g_x2 + (size_t)b * C2_OUT + ob * 81 + p;
        dst[0]   = fmaxf(a0, 0.f);
        dst[81]  = fmaxf(a1, 0.f);
        dst[162] = fmaxf(a2, 0.f);
        dst[243] = fmaxf(a3, 0.f);
    }
}

// ---------------- conv3: 64->64, 3x3 s1, 9x9 -> 7x7 ----------------
__global__ void __launch_bounds__(256) conv3_kernel(
    const float* __restrict__ k3, const float* __restrict__ c3) {
    extern __shared__ float img[];   // [64][9][9]
    int b = blockIdx.x, tid = threadIdx.x;
    const float* src = g_x2 + (size_t)b * C3_IN;
    for (int i = tid; i < C3_IN; i += 256) img[i] = src[i];
    __syncthreads();

    for (int item = tid; item < 16 * 49; item += 256) {
        int ob = (item / 49) * 4;
        int p  = item % 49;
        int oh = p / 7, ow = p % 7;
        float a0 = c3[ob], a1 = c3[ob+1], a2 = c3[ob+2], a3 = c3[ob+3];
        for (int c = 0; c < 64; ++c) {
            const float* ibase = img + c * 81 + oh * 9 + ow;
            const float* wb = k3 + (size_t)(ob * 64 + c) * 9;   // +576 per oc
            #pragma unroll
            for (int kh = 0; kh < 3; ++kh) {
                float v0 = ibase[kh * 9], v1 = ibase[kh * 9 + 1], v2 = ibase[kh * 9 + 2];
                const float* w0 = wb + kh * 3;
                a0 = fmaf(v0,w0[0],      fmaf(v1,w0[1],      fmaf(v2,w0[2],      a0)));
                a1 = fmaf(v0,w0[576],    fmaf(v1,w0[577],    fmaf(v2,w0[578],    a1)));
                a2 = fmaf(v0,w0[1152],   fmaf(v1,w0[1153],   fmaf(v2,w0[1154],   a2)));
                a3 = fmaf(v0,w0[1728],   fmaf(v1,w0[1729],   fmaf(v2,w0[1730],   a3)));
            }
        }
        float* dst = g_x3 + (size_t)b * C3_OUT + ob * 49 + p;
        dst[0]   = fmaxf(a0, 0.f);
        dst[49]  = fmaxf(a1, 0.f);
        dst[98]  = fmaxf(a2, 0.f);
        dst[147] = fmaxf(a3, 0.f);
    }
}

// ---------------- per-expert MLP (only assigned expert per sample) ----------------
__global__ void __launch_bounds__(64) mlp_kernel(
    const float* __restrict__ W1, const float* __restrict__ B1,
    const float* __restrict__ W2, const float* __restrict__ B2,
    const float* __restrict__ W3, const float* __restrict__ B3,
    const float* __restrict__ W4, const float* __restrict__ B4,
    const float* __restrict__ W5, const float* __restrict__ B5,
    const float* __restrict__ W6, const float* __restrict__ B6,
    float* __restrict__ out) {
    int e = blockIdx.x;
    int base = blockIdx.y * TB;
    int n = g_cnt[e] - base;
    if (n <= 0) return;
    if (n > TB) n = TB;

    __shared__ float tile[TB * DC];      // 28 KB
    __shared__ float hA[TB * 64], hB[TB * 64];
    __shared__ int   sid[TB];
    int j = threadIdx.x;                 // 64 threads = 64 hidden units

    if (j < TB) sid[j] = (j < n) ? g_idx[e * NB_MAX + base + j] : -1;
    __syncthreads();

    // ---- layer 1: [n,3136] @ W1[e] ----
    const float* W1e = W1 + (size_t)e * 3136 * 64;
    float acc[TB];
    #pragma unroll
    for (int s = 0; s < TB; ++s) acc[s] = 0.f;

    for (int dc = 0; dc < 3136; dc += DC) {
        __syncthreads();
        for (int i = j; i < TB * DC; i += 64) {
            int s = i / DC, d = i % DC;
            int bb = sid[s];
            tile[i] = (bb >= 0) ? g_x3[(size_t)bb * C3_OUT + dc + d] : 0.f;
        }
        __syncthreads();
        for (int d = 0; d < DC; d += 4) {
            float w0 = W1e[(size_t)(dc + d    ) * 64 + j];
            float w1 = W1e[(size_t)(dc + d + 1) * 64 + j];
            float w2 = W1e[(size_t)(dc + d + 2) * 64 + j];
            float w3 = W1e[(size_t)(dc + d + 3) * 64 + j];
            #pragma unroll
            for (int s = 0; s < TB; ++s) {
                float4 t = *(const float4*)(tile + s * DC + d);
                acc[s] = fmaf(t.x,w0, fmaf(t.y,w1, fmaf(t.z,w2, fmaf(t.w,w3, acc[s]))));
            }
        }
    }
    float b1 = B1[e * 64 + j];
    #pragma unroll
    for (int s = 0; s < TB; ++s) hA[s * 64 + j] = fmaxf(acc[s] + b1, 0.f);
    __syncthreads();

    // ---- layers 2..5: 64x64 ----
    const float* Ws[4] = {W2, W3, W4, W5};
    const float* Bs[4] = {B2, B3, B4, B5};
    float* hin = hA;
    float* hout = hB;
    for (int L = 0; L < 4; ++L) {
        const float* W = Ws[L] + (size_t)e * 4096;
        float bb = Bs[L][e * 64 + j];
        float a2[TB];
        #pragma unroll
        for (int s = 0; s < TB; ++s) a2[s] = bb;
        for (int k = 0; k < 64; ++k) {
            float w = W[k * 64 + j];
            #pragma unroll
            for (int s = 0; s < TB; ++s)
                a2[s] = fmaf(hin[s * 64 + k], w, a2[s]);
        }
        #pragma unroll
        for (int s = 0; s < TB; ++s) hout[s * 64 + j] = fmaxf(a2[s], 0.f);
        __syncthreads();
        float* t = hin; hin = hout; hout = t;
    }

    // ---- layer 6: 64 -> 6, no relu ----
    if (j < NA) {
        const float* W6e = W6 + (size_t)e * 64 * NA;
        float b6 = B6[e * NA + j];
        for (int s = 0; s < n; ++s) {
            float a = b6;
            #pragma unroll
            for (int k = 0; k < 64; ++k)
                a = fmaf(hin[s * 64 + k], W6e[k * NA + j], a);
            out[(size_t)sid[s] * NA + j] = a;
        }
    }
}

// ---------------- launch ----------------
extern "C" void kernel_launch(void* const* d_in, const int* in_sizes, int n_in,
                              void* d_out, int out_size) {
    const float* state = (const float*)d_in[0];
    const int*   rm    = (const int*)d_in[1];
    const float* k1 = (const float*)d_in[2];
    const float* c1 = (const float*)d_in[3];
    const float* k2 = (const float*)d_in[4];
    const float* c2 = (const float*)d_in[5];
    const float* k3 = (const float*)d_in[6];
    const float* c3 = (const float*)d_in[7];
    const float* W1 = (const float*)d_in[8];
    const float* B1 = (const float*)d_in[9];
    const float* W2 = (const float*)d_in[10];
    const float* B2 = (const float*)d_in[11];
    const float* W3 = (const float*)d_in[12];
    const float* B3 = (const float*)d_in[13];
    const float* W4 = (const float*)d_in[14];
    const float* B4 = (const float*)d_in[15];
    const float* W5 = (const float*)d_in[16];
    const float* B5 = (const float*)d_in[17];
    const float* W6 = (const float*)d_in[18];
    const float* B6 = (const float*)d_in[19];
    float* out = (float*)d_out;

    int nB = in_sizes[1];
    if (nB > NB_MAX) nB = NB_MAX;

    // conv1 needs 109 KB, conv2 51 KB dynamic smem (set every call; deterministic)
    cudaFuncSetAttribute(conv1_kernel, cudaFuncAttributeMaxDynamicSharedMemorySize,
                         (C1_IMG + C1_WT) * 4);
    cudaFuncSetAttribute(conv2_kernel, cudaFuncAttributeMaxDynamicSharedMemorySize,
                         C2_IN * 4);

    assign_kernel<<<1, 256>>>(rm, nB);
    conv1_kernel<<<nB, 256, (C1_IMG + C1_WT) * 4>>>(state, k1, c1);
    conv2_kernel<<<nB, 256, C2_IN * 4>>>(k2, c2);
    conv3_kernel<<<nB, 256, C3_IN * 4>>>(k3, c3);
    mlp_kernel<<<dim3(NE, (nB + TB - 1) / TB), 64>>>(
        W1, B1, W2, B2, W3, B3, W4, B4, W5, B5, W6, B6, out);
}

// round 3
// speedup vs baseline: 1.1789x; 1.1766x over previous
#include <cuda_runtime.h>
#include <cuda_bf16.h>

// ---------------- problem constants ----------------
#define NB_MAX   2048
#define C1_IMG   (3*84*84)     // 21168 floats per image
#define C1_OUT   (32*20*20)    // 12800 per image
#define C2_IN    C1_OUT
#define C2_OUT   (64*9*9)      // 5184
#define C3_IN    C2_OUT
#define C3_OUT   (64*7*7)      // 3136
#define NE       8
#define NA       6
#define TB       32            // samples per MLP block
#define DC       224           // D-chunk for layer1 (3136 = 14*224)

typedef unsigned long long ull;

// ---------------- scratch (device globals; no allocs allowed) ----------------
__device__ float g_x1[(size_t)NB_MAX * C1_OUT];   // ~105 MB
__device__ float g_x2[(size_t)NB_MAX * C2_OUT];   // ~42 MB
__device__ float g_x3[(size_t)NB_MAX * C3_OUT];   // ~26 MB
__device__ int   g_cnt[NE];
__device__ int   g_idx[NE * NB_MAX];

// ---------------- f32x2 helpers ----------------
__device__ __forceinline__ void fma2(ull& d, ull a, ull b) {
    asm("fma.rn.f32x2 %0, %1, %2, %0;" : "+l"(d) : "l"(a), "l"(b));
}
__device__ __forceinline__ ull pack2(float lo, float hi) {
    ull r; asm("mov.b64 %0, {%1, %2};" : "=l"(r) : "f"(lo), "f"(hi)); return r;
}
__device__ __forceinline__ float2 unpack2(ull v) {
    float2 r; asm("mov.b64 {%0, %1}, %2;" : "=f"(r.x), "=f"(r.y) : "l"(v)); return r;
}

// ---------------- expert bucketing (+ int64/int32 detection) ----------------
__global__ void assign_kernel(const int* __restrict__ rm32, int n) {
    __shared__ int s_is64;
    int tid = threadIdx.x;
    if (tid == 0) s_is64 = 1;
    __syncthreads();
    for (int i = tid; i < 256; i += blockDim.x)
        if (rm32[2*i + 1] != 0) atomicExch(&s_is64, 0);
    if (tid < NE) g_cnt[tid] = 0;
    __syncthreads();
    int is64 = s_is64;
    const long long* rm64 = (const long long*)rm32;
    for (int b = tid; b < n; b += blockDim.x) {
        int e = is64 ? (int)rm64[b] : rm32[b];
        int pos = atomicAdd(&g_cnt[e], 1);
        g_idx[e * NB_MAX + pos] = b;
    }
}

// ---------------- conv1: 3->32, 8x8 s4, 84x84 -> 20x20 ----------------
// kw-pair packing: acc halves hold even-kw / odd-kw partial sums.
// block = 128 (4 warps), 1 image. warp w handles output rows 5w..5w+4.
// lane = output channel (32).
__global__ void __launch_bounds__(128) conv1_kernel(
    const float* __restrict__ state, const float* __restrict__ k1,
    const float* __restrict__ c1) {
    extern __shared__ float sm[];
    float* img = sm;               // [3][84][84], planar
    float* wsm = sm + C1_IMG;      // packed weights: [c][kh][kwpair][32 lanes][2]
    int b = blockIdx.x, tid = threadIdx.x;
    const float* src = state + (size_t)b * C1_IMG;   // NHWC
    for (int i = tid; i < C1_IMG; i += 128) {
        int c = i % 3, hw = i / 3;
        img[c * 7056 + hw] = src[i];
    }
    for (int t = tid; t < 6144; t += 128) {
        int j = t / 192, rem = t % 192;
        int c = rem / 64, kh = (rem / 8) & 7, kw = rem & 7;
        int slot = (c * 8 + kh) * 4 + (kw >> 1);
        wsm[(slot * 32 + j) * 2 + (kw & 1)] = k1[t];
    }
    __syncthreads();

    int l = tid & 31, w = tid >> 5;
    float bias = c1[l];
    const ull* wv = (const ull*)wsm;

    for (int og = 0; og < 5; ++og) {
        int oh = w * 5 + og;
        ull acc[20];
        #pragma unroll
        for (int ow = 0; ow < 20; ++ow) acc[ow] = 0ULL;

        #pragma unroll
        for (int c = 0; c < 3; ++c) {
            for (int kh = 0; kh < 8; ++kh) {
                int ih = oh * 4 + kh;
                const ull* row = (const ull*)(img + c * 7056 + ih * 84);
                int wbase = ((c * 8 + kh) * 4) * 32 + l;
                ull wp0 = wv[wbase];
                ull wp1 = wv[wbase + 32];
                ull wp2 = wv[wbase + 64];
                ull wp3 = wv[wbase + 96];
                ull r0 = row[0], r1 = row[1], r2 = row[2], r3 = row[3];
                #pragma unroll
                for (int ow = 0; ow < 20; ++ow) {
                    fma2(acc[ow], r0, wp0);
                    fma2(acc[ow], r1, wp1);
                    fma2(acc[ow], r2, wp2);
                    fma2(acc[ow], r3, wp3);
                    if (ow < 19) {
                        r0 = r2; r1 = r3;
                        r2 = row[2 * ow + 4]; r3 = row[2 * ow + 5];
                    }
                }
            }
        }
        float* dst = g_x1 + (size_t)b * C1_OUT + l * 400 + oh * 20;
        #pragma unroll
        for (int ow = 0; ow < 20; ++ow) {
            float2 v = unpack2(acc[ow]);
            dst[ow] = fmaxf(v.x + v.y + bias, 0.f);
        }
    }
}

// ---------------- conv2: 32->64, 4x4 s2, 20x20 -> 9x9 ----------------
// input-channel-pair packing (c, c+16) pre-interleaved in SMEM as float2.
// block = 192: thread = (out channel j of 64, row-group g of 3), 1 image.
__global__ void __launch_bounds__(192) conv2_kernel(
    const float* __restrict__ k2, const float* __restrict__ c2) {
    extern __shared__ float2 img2[];   // [16 cp][400]
    int b = blockIdx.x, tid = threadIdx.x;
    const float* src = g_x1 + (size_t)b * C2_IN;
    for (int t = tid; t < 16 * 400; t += 192) {
        int cp = t / 400, i = t % 400;
        img2[t] = make_float2(src[cp * 400 + i], src[(cp + 16) * 400 + i]);
    }
    __syncthreads();

    int j = tid % 64, g = tid / 64;   // g in 0..2, output rows 3g..3g+2
    ull acc[27];
    #pragma unroll
    for (int p = 0; p < 27; ++p) acc[p] = 0ULL;

    const float* w0base = k2 + (size_t)j * 512;
    for (int cp = 0; cp < 16; ++cp) {
        ull wp[16];
        const float* wa = w0base + cp * 16;
        const float* wb = wa + 16 * 16;     // channel cp+16
        #pragma unroll
        for (int t = 0; t < 16; ++t) wp[t] = pack2(wa[t], wb[t]);

        const ull* ic = (const ull*)(img2 + cp * 400);
        #pragma unroll
        for (int d = 0; d < 8; ++d) {       // input row ih = 6g + d
            const ull* row = ic + (6 * g + d) * 20;
            ull r[20];
            #pragma unroll
            for (int x = 0; x < 20; ++x) r[x] = row[x];
            #pragma unroll
            for (int m = 0; m < 3; ++m) {   // local output row
                int kh = d - 2 * m;
                if (kh >= 0 && kh < 4) {
                    #pragma unroll
                    for (int ow = 0; ow < 9; ++ow) {
                        #pragma unroll
                        for (int kw = 0; kw < 4; ++kw)
                            fma2(acc[m * 9 + ow], r[2 * ow + kw], wp[kh * 4 + kw]);
                    }
                }
            }
        }
    }
    float bias = c2[j];
    float* dst = g_x2 + (size_t)b * C2_OUT + j * 81 + g * 27;
    #pragma unroll
    for (int p = 0; p < 27; ++p) {
        float2 v = unpack2(acc[p]);
        dst[p] = fmaxf(v.x + v.y + bias, 0.f);
    }
}

// ---------------- conv3: 64->64, 3x3 s1, 9x9 -> 7x7 ----------------
// input-channel-pair packing (c, c+32). block = 128 = 2 images x 64 threads.
// thread = output channel j; all 49 outputs in registers.
__global__ void __launch_bounds__(128) conv3_kernel(
    const float* __restrict__ k3, const float* __restrict__ c3, int nB) {
    __shared__ float2 img2[2 * 32 * 81];   // 41.5 KB
    int tid = threadIdx.x;
    int im = tid >> 6;                      // 0/1: image within block
    int b = blockIdx.x * 2 + im;
    if (b < nB) {
        const float* src = g_x2 + (size_t)b * C3_IN;
        int lt = tid & 63;
        for (int t = lt; t < 32 * 81; t += 64) {
            int cp = t / 81, i = t % 81;
            img2[im * 2592 + t] = make_float2(src[cp * 81 + i], src[(cp + 32) * 81 + i]);
        }
    }
    __syncthreads();
    if (b >= nB) return;

    int j = tid & 63;
    ull acc[49];
    #pragma unroll
    for (int p = 0; p < 49; ++p) acc[p] = 0ULL;

    const float* wj = k3 + (size_t)j * 576;
    for (int cp = 0; cp < 32; ++cp) {
        ull wp[9];
        const float* wa = wj + cp * 9;
        const float* wb = wa + 32 * 9;
        #pragma unroll
        for (int t = 0; t < 9; ++t) wp[t] = pack2(wa[t], wb[t]);

        const ull* ic = (const ull*)(img2 + im * 2592 + cp * 81);
        #pragma unroll
        for (int y = 0; y < 9; ++y) {
            ull r[9];
            #pragma unroll
            for (int x = 0; x < 9; ++x) r[x] = ic[y * 9 + x];
            #pragma unroll
            for (int kh = 0; kh < 3; ++kh) {
                int oh = y - kh;
                if (oh >= 0 && oh < 7) {
                    #pragma unroll
                    for (int ow = 0; ow < 7; ++ow) {
                        #pragma unroll
                        for (int kw = 0; kw < 3; ++kw)
                            fma2(acc[oh * 7 + ow], r[ow + kw], wp[kh * 3 + kw]);
                    }
                }
            }
        }
    }
    float bias = c3[j];
    float* dst = g_x3 + (size_t)b * C3_OUT + j * 49;
    #pragma unroll
    for (int p = 0; p < 49; ++p) {
        float2 v = unpack2(acc[p]);
        dst[p] = fmaxf(v.x + v.y + bias, 0.f);
    }
}

// ---------------- per-expert MLP (only assigned expert per sample) ----------------
__global__ void __launch_bounds__(64) mlp_kernel(
    const float* __restrict__ W1, const float* __restrict__ B1,
    const float* __restrict__ W2, const float* __restrict__ B2,
    const float* __restrict__ W3, const float* __restrict__ B3,
    const float* __restrict__ W4, const float* __restrict__ B4,
    const float* __restrict__ W5, const float* __restrict__ B5,
    const float* __restrict__ W6, const float* __restrict__ B6,
    float* __restrict__ out) {
    int e = blockIdx.x;
    int base = blockIdx.y * TB;
    int n = g_cnt[e] - base;
    if (n <= 0) return;
    if (n > TB) n = TB;

    __shared__ float tile[TB * DC];      // 28 KB
    __shared__ float hA[TB * 64], hB[TB * 64];
    __shared__ int   sid[TB];
    int j = threadIdx.x;

    if (j < TB) sid[j] = (j < n) ? g_idx[e * NB_MAX + base + j] : -1;
    __syncthreads();

    const float* W1e = W1 + (size_t)e * 3136 * 64;
    float acc[TB];
    #pragma unroll
    for (int s = 0; s < TB; ++s) acc[s] = 0.f;

    for (int dc = 0; dc < 3136; dc += DC) {
        __syncthreads();
        for (int i = j; i < TB * DC; i += 64) {
            int s = i / DC, d = i % DC;
            int bb = sid[s];
            tile[i] = (bb >= 0) ? g_x3[(size_t)bb * C3_OUT + dc + d] : 0.f;
        }
        __syncthreads();
        for (int d = 0; d < DC; d += 4) {
            float w0 = W1e[(size_t)(dc + d    ) * 64 + j];
            float w1 = W1e[(size_t)(dc + d + 1) * 64 + j];
            float w2 = W1e[(size_t)(dc + d + 2) * 64 + j];
            float w3 = W1e[(size_t)(dc + d + 3) * 64 + j];
            #pragma unroll
            for (int s = 0; s < TB; ++s) {
                float4 t = *(const float4*)(tile + s * DC + d);
                acc[s] = fmaf(t.x,w0, fmaf(t.y,w1, fmaf(t.z,w2, fmaf(t.w,w3, acc[s]))));
            }
        }
    }
    float b1 = B1[e * 64 + j];
    #pragma unroll
    for (int s = 0; s < TB; ++s) hA[s * 64 + j] = fmaxf(acc[s] + b1, 0.f);
    __syncthreads();

    const float* Ws[4] = {W2, W3, W4, W5};
    const float* Bs[4] = {B2, B3, B4, B5};
    float* hin = hA;
    float* hout = hB;
    for (int L = 0; L < 4; ++L) {
        const float* W = Ws[L] + (size_t)e * 4096;
        float bb = Bs[L][e * 64 + j];
        float a2[TB];
        #pragma unroll
        for (int s = 0; s < TB; ++s) a2[s] = bb;
        for (int k = 0; k < 64; ++k) {
            float w = W[k * 64 + j];
            #pragma unroll
            for (int s = 0; s < TB; ++s)
                a2[s] = fmaf(hin[s * 64 + k], w, a2[s]);
        }
        #pragma unroll
        for (int s = 0; s < TB; ++s) hout[s * 64 + j] = fmaxf(a2[s], 0.f);
        __syncthreads();
        float* t = hin; hin = hout; hout = t;
    }

    if (j < NA) {
        const float* W6e = W6 + (size_t)e * 64 * NA;
        float b6 = B6[e * NA + j];
        for (int s = 0; s < n; ++s) {
            float a = b6;
            #pragma unroll
            for (int k = 0; k < 64; ++k)
                a = fmaf(hin[s * 64 + k], W6e[k * NA + j], a);
            out[(size_t)sid[s] * NA + j] = a;
        }
    }
}

// ---------------- launch ----------------
extern "C" void kernel_launch(void* const* d_in, const int* in_sizes, int n_in,
                              void* d_out, int out_size) {
    const float* state = (const float*)d_in[0];
    const int*   rm    = (const int*)d_in[1];
    const float* k1 = (const float*)d_in[2];
    const float* c1 = (const float*)d_in[3];
    const float* k2 = (const float*)d_in[4];
    const float* c2 = (const float*)d_in[5];
    const float* k3 = (const float*)d_in[6];
    const float* c3 = (const float*)d_in[7];
    const float* W1 = (const float*)d_in[8];
    const float* B1 = (const float*)d_in[9];
    const float* W2 = (const float*)d_in[10];
    const float* B2 = (const float*)d_in[11];
    const float* W3 = (const float*)d_in[12];
    const float* B3 = (const float*)d_in[13];
    const float* W4 = (const float*)d_in[14];
    const float* B4 = (const float*)d_in[15];
    const float* W5 = (const float*)d_in[16];
    const float* B5 = (const float*)d_in[17];
    const float* W6 = (const float*)d_in[18];
    const float* B6 = (const float*)d_in[19];
    float* out = (float*)d_out;

    int nB = in_sizes[1];
    if (nB > NB_MAX) nB = NB_MAX;

    const int conv1_smem = (C1_IMG + 6144) * 4;       // 109248 B
    const int conv2_smem = 16 * 400 * 8;              // 51200 B
    cudaFuncSetAttribute(conv1_kernel, cudaFuncAttributeMaxDynamicSharedMemorySize,
                         conv1_smem);
    cudaFuncSetAttribute(conv2_kernel, cudaFuncAttributeMaxDynamicSharedMemorySize,
                         conv2_smem);

    assign_kernel<<<1, 256>>>(rm, nB);
    conv1_kernel<<<nB, 128, conv1_smem>>>(state, k1, c1);
    conv2_kernel<<<nB, 192, conv2_smem>>>(k2, c2);
    conv3_kernel<<<(nB + 1) / 2, 128>>>(k3, c3, nB);
    mlp_kernel<<<dim3(NE, (nB + TB - 1) / TB), 64>>>(
        W1, B1, W2, B2, W3, B3, W4, B4, W5, B5, W6, B6, out);
}

// round 5
// speedup vs baseline: 2.0048x; 1.7006x over previous
#include <cuda_runtime.h>
#include <cuda_bf16.h>

// ---------------- problem constants ----------------
#define NB_MAX   2048
#define C1_IMG   (3*84*84)     // 21168
#define C1_OUT   (32*20*20)    // 12800
#define C2_IN    C1_OUT
#define C2_OUT   (64*9*9)      // 5184
#define C3_IN    C2_OUT
#define C3_OUT   (64*7*7)      // 3136
#define NE       8
#define NA       6
#define TB       32
#define DC       224           // 3136 = 14*224

typedef unsigned long long ull;

// ---------------- scratch (device globals) ----------------
__device__ float g_x1[(size_t)NB_MAX * C1_OUT];
__device__ float g_x2[(size_t)NB_MAX * C2_OUT];
__device__ float g_x3[(size_t)NB_MAX * C3_OUT];
__device__ int   g_cnt[NE];
__device__ int   g_idx[NE * NB_MAX];
// prepacked weights
__device__ ull   g_wp1[768 * 32];        // conv1: [(c*8+kh)*4+p][lane oc]
__device__ ull   g_wp2[256 * 64];        // conv2: [(c*4+kh)*2+p][j]
__device__ ull   g_wp3[288 * 64];        // conv3: [cp*9+t][j]
__device__ float g_W1t[NE * 64 * 3136];  // [e][j][d]

// ---------------- f32x2 helpers ----------------
__device__ __forceinline__ void fma2(ull& d, ull a, ull b) {
    asm("fma.rn.f32x2 %0, %1, %2, %0;" : "+l"(d) : "l"(a), "l"(b));
}
__device__ __forceinline__ ull pack2(float lo, float hi) {
    ull r; asm("mov.b64 %0, {%1, %2};" : "=l"(r) : "f"(lo), "f"(hi)); return r;
}
__device__ __forceinline__ float2 unpack2(ull v) {
    float2 r; asm("mov.b64 {%0, %1}, %2;" : "=f"(r.x), "=f"(r.y) : "l"(v)); return r;
}

// ---------------- weight prepack + W1 transpose ----------------
__global__ void prep_kernel(const float* __restrict__ k1, const float* __restrict__ k2,
                            const float* __restrict__ k3, const float* __restrict__ W1) {
    int t0 = blockIdx.x * blockDim.x + threadIdx.x;
    int stride = gridDim.x * blockDim.x;
    for (int t = t0; t < 768 * 32; t += stride) {
        int slot = t >> 5, j = t & 31;
        int c = slot >> 5, kh = (slot >> 2) & 7, p = slot & 3;
        int base = j * 192 + c * 64 + kh * 8 + 2 * p;
        g_wp1[t] = pack2(k1[base], k1[base + 1]);
    }
    for (int t = t0; t < 256 * 64; t += stride) {
        int slot = t >> 6, j = t & 63;
        int c = slot >> 3, kh = (slot >> 1) & 3, p = slot & 1;
        int base = j * 512 + c * 16 + kh * 4 + 2 * p;
        g_wp2[t] = pack2(k2[base], k2[base + 1]);
    }
    for (int t = t0; t < 288 * 64; t += stride) {
        int slot = t >> 6, j = t & 63;
        int cp = slot / 9, tap = slot % 9;
        g_wp3[t] = pack2(k3[j * 576 + cp * 9 + tap], k3[j * 576 + (cp + 32) * 9 + tap]);
    }
    for (int i = t0; i < NE * 64 * 3136; i += stride) {
        int e = i / 200704, rem = i % 200704;
        int j = rem / 3136, d = rem % 3136;
        g_W1t[i] = W1[e * 200704 + d * 64 + j];
    }
}

// ---------------- expert bucketing ----------------
__global__ void assign_kernel(const int* __restrict__ rm32, int n) {
    __shared__ int s_is64;
    int tid = threadIdx.x;
    if (tid == 0) s_is64 = 1;
    __syncthreads();
    for (int i = tid; i < 256; i += blockDim.x)
        if (rm32[2*i + 1] != 0) atomicExch(&s_is64, 0);
    if (tid < NE) g_cnt[tid] = 0;
    __syncthreads();
    int is64 = s_is64;
    const long long* rm64 = (const long long*)rm32;
    for (int b = tid; b < n; b += blockDim.x) {
        int e = is64 ? (int)rm64[b] : rm32[b];
        int pos = atomicAdd(&g_cnt[e], 1);
        g_idx[e * NB_MAX + pos] = b;
    }
}

// ---------------- conv1: 3->32, 8x8 s4, 84x84 -> 20x20 ----------------
// 160 threads (5 warps): warp w -> output rows 4w..4w+3; lane = oc.
// og loop kept rolled (#pragma unroll 1) so only one acc[20] is live -> no spill.
__global__ void __launch_bounds__(160) conv1_kernel(
    const float* __restrict__ state, const float* __restrict__ c1) {
    extern __shared__ float img[];   // [3][7056]
    int b = blockIdx.x, tid = threadIdx.x;
    const float* src = state + (size_t)b * C1_IMG;   // NHWC
    for (int hw = tid; hw < 7056; hw += 160) {
        float v0 = src[hw * 3], v1 = src[hw * 3 + 1], v2 = src[hw * 3 + 2];
        img[hw] = v0; img[7056 + hw] = v1; img[14112 + hw] = v2;
    }
    __syncthreads();

    int l = tid & 31, w = tid >> 5;
    float bias = c1[l];

    #pragma unroll 1
    for (int og = 0; og < 4; ++og) {
        int oh = w * 4 + og;
        ull acc[20];
        #pragma unroll
        for (int ow = 0; ow < 20; ++ow) acc[ow] = 0ULL;

        #pragma unroll 1
        for (int c = 0; c < 3; ++c) {
            #pragma unroll
            for (int kh = 0; kh < 8; ++kh) {
                int ih = oh * 4 + kh;
                const ull* row = (const ull*)(img + c * 7056 + ih * 84);
                int wbase = ((c * 8 + kh) * 4) * 32 + l;
                ull wp0 = g_wp1[wbase];
                ull wp1 = g_wp1[wbase + 32];
                ull wp2 = g_wp1[wbase + 64];
                ull wp3 = g_wp1[wbase + 96];
                ull r0 = row[0], r1 = row[1], r2 = row[2], r3 = row[3];
                #pragma unroll
                for (int ow = 0; ow < 20; ++ow) {
                    fma2(acc[ow], r0, wp0);
                    fma2(acc[ow], r1, wp1);
                    fma2(acc[ow], r2, wp2);
                    fma2(acc[ow], r3, wp3);
                    if (ow < 19) {
                        r0 = r2; r1 = r3;
                        r2 = row[2 * ow + 4]; r3 = row[2 * ow + 5];
                    }
                }
            }
        }
        float* dst = g_x1 + (size_t)b * C1_OUT + l * 400 + oh * 20;
        #pragma unroll
        for (int ow = 0; ow < 20; ++ow) {
            float2 v = unpack2(acc[ow]);
            dst[ow] = fmaxf(v.x + v.y + bias, 0.f);
        }
    }
}

// ---------------- conv2: 32->64, 4x4 s2, 20x20 -> 9x9 ----------------
// kw-pair packing; planar smem. 192 threads: j = tid%64, g = tid/64 (rows 3g..3g+2).
__global__ void __launch_bounds__(192) conv2_kernel(const float* __restrict__ c2) {
    __shared__ float img[C2_IN];     // 25.6 KB
    int b = blockIdx.x, tid = threadIdx.x;
    const float* src = g_x1 + (size_t)b * C2_IN;
    for (int i = tid; i < C2_IN; i += 192) img[i] = src[i];
    __syncthreads();

    int j = tid % 64, g = tid / 64;
    ull acc[27];
    #pragma unroll
    for (int p = 0; p < 27; ++p) acc[p] = 0ULL;

    #pragma unroll 1
    for (int c = 0; c < 32; ++c) {
        ull wp[8];
        #pragma unroll
        for (int t = 0; t < 8; ++t) wp[t] = g_wp2[(c * 8 + t) * 64 + j];

        const ull* ic = (const ull*)(img + c * 400);
        #pragma unroll
        for (int d = 0; d < 8; ++d) {       // input row ih = 6g + d
            const ull* row = ic + (6 * g + d) * 10;
            ull r[10];
            #pragma unroll
            for (int x = 0; x < 10; ++x) r[x] = row[x];
            #pragma unroll
            for (int m = 0; m < 3; ++m) {
                int kh = d - 2 * m;
                if (kh >= 0 && kh < 4) {
                    #pragma unroll
                    for (int ow = 0; ow < 9; ++ow) {
                        fma2(acc[m * 9 + ow], r[ow],     wp[kh * 2]);
                        fma2(acc[m * 9 + ow], r[ow + 1], wp[kh * 2 + 1]);
                    }
                }
            }
        }
    }
    float bias = c2[j];
    float* dst = g_x2 + (size_t)b * C2_OUT + j * 81 + g * 27;
    #pragma unroll
    for (int p = 0; p < 27; ++p) {
        float2 v = unpack2(acc[p]);
        dst[p] = fmaxf(v.x + v.y + bias, 0.f);
    }
}

// ---------------- conv3: 64->64, 3x3 s1, 9x9 -> 7x7 ----------------
template<int OH0, int NOH>
__device__ __forceinline__ void conv3_compute(const ull* icbase, int j, float bias,
                                              float* __restrict__ dst) {
    ull acc[NOH * 7];
    #pragma unroll
    for (int p = 0; p < NOH * 7; ++p) acc[p] = 0ULL;

    #pragma unroll 1
    for (int cp = 0; cp < 32; ++cp) {
        ull wp[9];
        #pragma unroll
        for (int t = 0; t < 9; ++t) wp[t] = g_wp3[(cp * 9 + t) * 64 + j];

        const ull* ic = icbase + cp * 81;
        #pragma unroll
        for (int y = OH0; y < OH0 + NOH + 2; ++y) {
            ull r[9];
            #pragma unroll
            for (int x = 0; x < 9; ++x) r[x] = ic[y * 9 + x];
            #pragma unroll
            for (int kh = 0; kh < 3; ++kh) {
                int oh = y - kh;
                if (oh >= OH0 && oh < OH0 + NOH) {
                    #pragma unroll
                    for (int ow = 0; ow < 7; ++ow)
                        #pragma unroll
                        for (int kw = 0; kw < 3; ++kw)
                            fma2(acc[(oh - OH0) * 7 + ow], r[ow + kw], wp[kh * 3 + kw]);
                }
            }
        }
    }
    #pragma unroll
    for (int p = 0; p < NOH * 7; ++p) {
        float2 v = unpack2(acc[p]);
        dst[OH0 * 7 + p] = fmaxf(v.x + v.y + bias, 0.f);
    }
}

// 256 threads = 2 images x 2 row-halves x 64 oc.
__global__ void __launch_bounds__(256) conv3_kernel(const float* __restrict__ c3, int nB) {
    extern __shared__ float2 im2[];   // [2][32][81] channel-pair interleaved
    int tid = threadIdx.x;
    int im = tid >> 7;
    int b = blockIdx.x * 2 + im;
    if (b < nB) {
        const float* src = g_x2 + (size_t)b * C3_IN;
        int lt = tid & 127;
        for (int t = lt; t < 32 * 81; t += 128) {
            int cp = t / 81, i = t % 81;
            im2[im * 2592 + t] = make_float2(src[cp * 81 + i], src[(cp + 32) * 81 + i]);
        }
    }
    __syncthreads();
    if (b >= nB) return;

    int half = (tid >> 6) & 1, j = tid & 63;
    float bias = c3[j];
    const ull* ic = (const ull*)(im2 + im * 2592);
    float* dst = g_x3 + (size_t)b * C3_OUT + j * 49;
    if (half == 0) conv3_compute<0, 4>(ic, j, bias, dst);
    else           conv3_compute<4, 3>(ic, j, bias, dst);
}

// ---------------- per-expert MLP ----------------
__global__ void __launch_bounds__(64) mlp_kernel(
    const float* __restrict__ B1,
    const float* __restrict__ W2, const float* __restrict__ B2,
    const float* __restrict__ W3, const float* __restrict__ B3,
    const float* __restrict__ W4, const float* __restrict__ B4,
    const float* __restrict__ W5, const float* __restrict__ B5,
    const float* __restrict__ W6, const float* __restrict__ B6,
    float* __restrict__ out) {
    int e = blockIdx.x;
    int base = blockIdx.y * TB;
    int n = g_cnt[e] - base;
    if (n <= 0) return;
    if (n > TB) n = TB;

    __shared__ float tile[TB * DC];
    __shared__ float hA[TB * 64], hB[TB * 64];
    __shared__ int   sid[TB];
    int j = threadIdx.x;

    if (j < TB) sid[j] = (j < n) ? g_idx[e * NB_MAX + base + j] : -1;
    __syncthreads();

    const float* wrow = g_W1t + (size_t)e * 200704 + (size_t)j * 3136;
    float acc[TB];
    #pragma unroll
    for (int s = 0; s < TB; ++s) acc[s] = 0.f;

    #pragma unroll 1
    for (int dc = 0; dc < 3136; dc += DC) {
        __syncthreads();
        for (int i = j; i < TB * DC; i += 64) {
            int s = i / DC, d = i % DC;
            int bb = sid[s];
            tile[i] = (bb >= 0) ? g_x3[(size_t)bb * C3_OUT + dc + d] : 0.f;
        }
        __syncthreads();
        #pragma unroll 1
        for (int d = 0; d < DC; d += 8) {
            float4 wa = *(const float4*)(wrow + dc + d);
            float4 wb = *(const float4*)(wrow + dc + d + 4);
            #pragma unroll
            for (int s = 0; s < TB; ++s) {
                float4 t1 = *(const float4*)(tile + s * DC + d);
                float4 t2 = *(const float4*)(tile + s * DC + d + 4);
                float a = acc[s];
                a = fmaf(t1.x, wa.x, a); a = fmaf(t1.y, wa.y, a);
                a = fmaf(t1.z, wa.z, a); a = fmaf(t1.w, wa.w, a);
                a = fmaf(t2.x, wb.x, a); a = fmaf(t2.y, wb.y, a);
                a = fmaf(t2.z, wb.z, a); a = fmaf(t2.w, wb.w, a);
                acc[s] = a;
            }
        }
    }
    float b1 = B1[e * 64 + j];
    #pragma unroll
    for (int s = 0; s < TB; ++s) hA[s * 64 + j] = fmaxf(acc[s] + b1, 0.f);
    __syncthreads();

    const float* Ws[4] = {W2, W3, W4, W5};
    const float* Bs[4] = {B2, B3, B4, B5};
    float* hin = hA;
    float* hout = hB;
    #pragma unroll 1
    for (int L = 0; L < 4; ++L) {
        const float* W = Ws[L] + (size_t)e * 4096;
        float bb = Bs[L][e * 64 + j];
        float a2[TB];
        #pragma unroll
        for (int s = 0; s < TB; ++s) a2[s] = bb;
        for (int k = 0; k < 64; ++k) {
            float w = W[k * 64 + j];
            #pragma unroll
            for (int s = 0; s < TB; ++s)
                a2[s] = fmaf(hin[s * 64 + k], w, a2[s]);
        }
        #pragma unroll
        for (int s = 0; s < TB; ++s) hout[s * 64 + j] = fmaxf(a2[s], 0.f);
        __syncthreads();
        float* t = hin; hin = hout; hout = t;
    }

    if (j < NA) {
        const float* W6e = W6 + (size_t)e * 64 * NA;
        float b6 = B6[e * NA + j];
        for (int s = 0; s < n; ++s) {
            float a = b6;
            #pragma unroll
            for (int k = 0; k < 64; ++k)
                a = fmaf(hin[s * 64 + k], W6e[k * NA + j], a);
            out[(size_t)sid[s] * NA + j] = a;
        }
    }
}

// ---------------- launch ----------------
extern "C" void kernel_launch(void* const* d_in, const int* in_sizes, int n_in,
                              void* d_out, int out_size) {
    const float* state = (const float*)d_in[0];
    const int*   rm    = (const int*)d_in[1];
    const float* k1 = (const float*)d_in[2];
    const float* c1 = (const float*)d_in[3];
    const float* k2 = (const float*)d_in[4];
    const float* c2 = (const float*)d_in[5];
    const float* k3 = (const float*)d_in[6];
    const float* c3 = (const float*)d_in[7];
    const float* W1 = (const float*)d_in[8];
    const float* B1 = (const float*)d_in[9];
    const float* W2 = (const float*)d_in[10];
    const float* B2 = (const float*)d_in[11];
    const float* W3 = (const float*)d_in[12];
    const float* B3 = (const float*)d_in[13];
    const float* W4 = (const float*)d_in[14];
    const float* B4 = (const float*)d_in[15];
    const float* W5 = (const float*)d_in[16];
    const float* B5 = (const float*)d_in[17];
    const float* W6 = (const float*)d_in[18];
    const float* B6 = (const float*)d_in[19];
    float* out = (float*)d_out;

    int nB = in_sizes[1];
    if (nB > NB_MAX) nB = NB_MAX;

    const int conv1_smem = C1_IMG * 4;       // 84672 B
    const int conv3_smem = 2 * 2592 * 8;     // 82944 B
    cudaFuncSetAttribute(conv1_kernel, cudaFuncAttributeMaxDynamicSharedMemorySize,
                         conv1_smem);
    cudaFuncSetAttribute(conv3_kernel, cudaFuncAttributeMaxDynamicSharedMemorySize,
                         conv3_smem);

    prep_kernel<<<512, 256>>>(k1, k2, k3, W1);
    assign_kernel<<<1, 256>>>(rm, nB);
    conv1_kernel<<<nB, 160, conv1_smem>>>(state, c1);
    conv2_kernel<<<nB, 192>>>(c2);
    conv3_kernel<<<(nB + 1) / 2, 256, conv3_smem>>>(c3, nB);
    mlp_kernel<<<dim3(NE, (nB + TB - 1) / TB), 64>>>(
        B1, W2, B2, W3, B3, W4, B4, W5, B5, W6, B6, out);
}

// round 7
// speedup vs baseline: 2.4547x; 1.2244x over previous
#include <cuda_runtime.h>
#include <cuda_bf16.h>
#include <cstdint>

// ---------------- problem constants ----------------
#define NB_MAX   2048
#define NE       8
#define NA       6
#define TB       32
#define DC       224           // 3136 = 14*224
#define C3_OUT   3136

// ---------------- scratch (device globals; no allocs allowed) ----------------
// activations, POSITION-MAJOR: [b][pos][channels]
__device__ float g_x1[(size_t)NB_MAX * 400 * 32];
__device__ float g_x2[(size_t)NB_MAX * 81 * 64];
__device__ float g_x3[(size_t)NB_MAX * 49 * 64];
__device__ int   g_cnt[NE];
__device__ int   g_idx[NE * NB_MAX];
// conv weights prepacked [N][K+8] bf16, hi/lo split (pad for bank alignment)
__device__ unsigned short g_B1h[32 * 200],  g_B1l[32 * 200];
__device__ unsigned short g_B2h[64 * 520],  g_B2l[64 * 520];
__device__ unsigned short g_B3h[64 * 584],  g_B3l[64 * 584];
// W1 transposed+permuted: [e][j][d'] with d' = p*64 + c  (matches g_x3 pm layout)
__device__ float g_W1t[NE * 64 * 3136];

// ---------------- mma.sync helper ----------------
__device__ __forceinline__ void mma_bf16(float* c, uint32_t a0, uint32_t a1,
                                         uint32_t a2, uint32_t a3,
                                         uint32_t b0, uint32_t b1) {
    asm volatile(
        "mma.sync.aligned.m16n8k16.row.col.f32.bf16.bf16.f32 "
        "{%0,%1,%2,%3}, {%4,%5,%6,%7}, {%8,%9}, {%0,%1,%2,%3};"
        : "+f"(c[0]), "+f"(c[1]), "+f"(c[2]), "+f"(c[3])
        : "r"(a0), "r"(a1), "r"(a2), "r"(a3), "r"(b0), "r"(b1));
}

// ---------------- bf16 hi/lo packing ----------------
__device__ __forceinline__ void pack8(const float* v, uint4& H, uint4& L) {
    unsigned hw[4], lw[4];
    #pragma unroll
    for (int q = 0; q < 4; ++q) {
        float a = v[2*q], b = v[2*q+1];
        __nv_bfloat162 hh = __floats2bfloat162_rn(a, b);
        float ra = a - __bfloat162float(__low2bfloat16(hh));
        float rb = b - __bfloat162float(__high2bfloat16(hh));
        __nv_bfloat162 ll = __floats2bfloat162_rn(ra, rb);
        hw[q] = *(unsigned*)&hh; lw[q] = *(unsigned*)&ll;
    }
    H = make_uint4(hw[0], hw[1], hw[2], hw[3]);
    L = make_uint4(lw[0], lw[1], lw[2], lw[3]);
}
// A tile row = 72 bf16 (144 B); store 8 values at (r, kin0)
__device__ __forceinline__ void store8p(char* pAh, char* pAl, int r, int kin0,
                                        const float* v) {
    int off = r * 144 + kin0 * 2;
    uint4 H, L; pack8(v, H, L);
    *(uint4*)(pAh + off) = H;
    *(uint4*)(pAl + off) = L;
}

// ---------------- weight prepack + W1 transpose ----------------
__global__ void prep_kernel(const float* __restrict__ k1, const float* __restrict__ k2,
                            const float* __restrict__ k3, const float* __restrict__ W1) {
    int t0 = blockIdx.x * blockDim.x + threadIdx.x;
    int stride = gridDim.x * blockDim.x;
    // conv1: kk = c*64 + kh*8 + kw  (== original k1 inner order)
    for (int t = t0; t < 32 * 192; t += stride) {
        int j = t / 192, kk = t % 192;
        float w = k1[j * 192 + kk];
        __nv_bfloat16 h = __float2bfloat16_rn(w);
        __nv_bfloat16 l = __float2bfloat16_rn(w - __bfloat162float(h));
        g_B1h[j * 200 + kk] = *(unsigned short*)&h;
        g_B1l[j * 200 + kk] = *(unsigned short*)&l;
    }
    // conv2: kk = tap*32 + c, tap = kh*4 + kw
    for (int t = t0; t < 64 * 512; t += stride) {
        int j = t / 512, kk = t % 512;
        int tap = kk >> 5, c = kk & 31, kh = tap >> 2, kw = tap & 3;
        float w = k2[j * 512 + c * 16 + kh * 4 + kw];
        __nv_bfloat16 h = __float2bfloat16_rn(w);
        __nv_bfloat16 l = __float2bfloat16_rn(w - __bfloat162float(h));
        g_B2h[j * 520 + kk] = *(unsigned short*)&h;
        g_B2l[j * 520 + kk] = *(unsigned short*)&l;
    }
    // conv3: kk = tap*64 + c, tap = kh*3 + kw
    for (int t = t0; t < 64 * 576; t += stride) {
        int j = t / 576, kk = t % 576;
        int tap = kk >> 6, c = kk & 63;
        float w = k3[j * 576 + c * 9 + tap];
        __nv_bfloat16 h = __float2bfloat16_rn(w);
        __nv_bfloat16 l = __float2bfloat16_rn(w - __bfloat162float(h));
        g_B3h[j * 584 + kk] = *(unsigned short*)&h;
        g_B3l[j * 584 + kk] = *(unsigned short*)&l;
    }
    // W1t: [e][j][d'] with d' = p*64 + c  <->  original d = c*49 + p
    for (int i = t0; i < NE * 64 * 3136; i += stride) {
        int e = i / 200704, rem = i % 200704;
        int j = rem / 3136, dp = rem % 3136;
        int p = dp >> 6, c = dp & 63;
        g_W1t[i] = W1[e * 200704 + (c * 49 + p) * 64 + j];
    }
}

// ---------------- expert bucketing ----------------
__global__ void assign_kernel(const int* __restrict__ rm32, int n) {
    __shared__ int s_is64;
    int tid = threadIdx.x;
    if (tid == 0) s_is64 = 1;
    __syncthreads();
    for (int i = tid; i < 256; i += blockDim.x)
        if (rm32[2*i + 1] != 0) atomicExch(&s_is64, 0);
    if (tid < NE) g_cnt[tid] = 0;
    __syncthreads();
    int is64 = s_is64;
    const long long* rm64 = (const long long*)rm32;
    for (int b = tid; b < n; b += blockDim.x) {
        int e = is64 ? (int)rm64[b] : rm32[b];
        int pos = atomicAdd(&g_cnt[e], 1);
        g_idx[e * NB_MAX + pos] = b;
    }
}

// ---------------- conv-as-GEMM via mma.sync bf16 (hi/lo 3-pass) ------------
// CONV=1: 3->32  8x8 s4  (K=192, N=32, POS=400)
// CONV=2: 32->64 4x4 s2  (K=512, N=64, POS=81)
// CONV=3: 64->64 3x3 s1  (K=576, N=64, POS=49)
template<int CONV>
__global__ void __launch_bounds__(256) conv_mma_kernel(
    const float* __restrict__ state, const float* __restrict__ bias, int MTOT) {
    constexpr int KCH = (CONV == 1) ? 3 : ((CONV == 2) ? 8 : 9);
    constexpr int N   = (CONV == 1) ? 32 : 64;
    constexpr int KW  = (CONV == 1) ? 100 : ((CONV == 2) ? 260 : 292); // B row words
    constexpr int POS = (CONV == 1) ? 400 : ((CONV == 2) ? 81 : 49);
    constexpr int NT  = N / 8;

    extern __shared__ char smem[];
    char* pAh = smem;                    // [128][72] bf16 hi
    char* pAl = smem + 18432;            // lo
    uint32_t* Aw  = (uint32_t*)pAh;
    uint32_t* AwL = (uint32_t*)pAl;
    uint32_t* Bw  = (uint32_t*)(smem + 36864);   // [N][KW] words, hi
    uint32_t* BwL = Bw + N * KW;                  // lo

    int tid = threadIdx.x, wid = tid >> 5, lane = tid & 31;

    // copy prepacked B into SMEM
    {
        const uint4* gBh = (CONV == 1) ? (const uint4*)g_B1h
                         : (CONV == 2) ? (const uint4*)g_B2h : (const uint4*)g_B3h;
        const uint4* gBl = (CONV == 1) ? (const uint4*)g_B1l
                         : (CONV == 2) ? (const uint4*)g_B2l : (const uint4*)g_B3l;
        uint4* sBh = (uint4*)Bw;
        uint4* sBl = (uint4*)BwL;
        int nu = N * KW / 4;
        for (int i = tid; i < nu; i += 256) { sBh[i] = gBh[i]; sBl[i] = gBl[i]; }
    }

    long long tb = (long long)blockIdx.x * 128;
    int r = tid >> 1, half = tid & 1;
    long long gp = tb + r;
    if (gp >= MTOT) gp = MTOT - 1;
    int b = (int)(gp / POS), p = (int)(gp % POS);

    float C[NT][4];
    #pragma unroll
    for (int nt = 0; nt < NT; ++nt)
        #pragma unroll
        for (int q = 0; q < 4; ++q) C[nt][q] = 0.f;

    int arow = wid * 16 + (lane >> 2);
    int ab0 = arow * 36 + (lane & 3);

    for (int ch = 0; ch < KCH; ++ch) {
        __syncthreads();   // previous iter's reads done (also covers B copy on ch=0)
        // ---- build A chunk (im2col gather -> bf16 hi/lo) ----
        float v[8];
        if (CONV == 1) {
            int oh = p / 20, ow = p % 20;
            #pragma unroll
            for (int u = 0; u < 4; ++u) {
                int kh = half * 4 + u;
                const float* s = state + ((size_t)(b * 84 + oh * 4 + kh) * 84 + ow * 4) * 3 + ch;
                #pragma unroll
                for (int q = 0; q < 8; ++q) v[q] = s[q * 3];
                store8p(pAh, pAl, r, kh * 8, v);
            }
        } else if (CONV == 2) {
            int oh = p / 9, ow = p % 9;
            int tap = ch * 2 + half, kh = tap >> 2, kw = tap & 3;
            const float* s = g_x1 + ((size_t)b * 400 + (2*oh + kh) * 20 + (2*ow + kw)) * 32;
            #pragma unroll
            for (int u = 0; u < 4; ++u) {
                float4 f0 = ((const float4*)s)[u*2], f1 = ((const float4*)s)[u*2 + 1];
                v[0]=f0.x; v[1]=f0.y; v[2]=f0.z; v[3]=f0.w;
                v[4]=f1.x; v[5]=f1.y; v[6]=f1.z; v[7]=f1.w;
                store8p(pAh, pAl, r, half * 32 + u * 8, v);
            }
        } else {
            int oh = p / 7, ow = p % 7;
            int kh = ch / 3, kw = ch % 3;
            const float* s = g_x2 + ((size_t)b * 81 + (oh + kh) * 9 + (ow + kw)) * 64 + half * 32;
            #pragma unroll
            for (int u = 0; u < 4; ++u) {
                float4 f0 = ((const float4*)s)[u*2], f1 = ((const float4*)s)[u*2 + 1];
                v[0]=f0.x; v[1]=f0.y; v[2]=f0.z; v[3]=f0.w;
                v[4]=f1.x; v[5]=f1.y; v[6]=f1.z; v[7]=f1.w;
                store8p(pAh, pAl, r, half * 32 + u * 8, v);
            }
        }
        __syncthreads();

        // ---- 4 k16 steps x NT n-tiles x 3-pass split ----
        #pragma unroll
        for (int k16 = 0; k16 < 4; ++k16) {
            int ab = ab0 + k16 * 8;
            uint32_t ah0 = Aw[ab],      ah1 = Aw[ab + 288];
            uint32_t ah2 = Aw[ab + 4],  ah3 = Aw[ab + 292];
            uint32_t al0 = AwL[ab],     al1 = AwL[ab + 288];
            uint32_t al2 = AwL[ab + 4], al3 = AwL[ab + 292];
            int kb = (ch * 4 + k16) * 8 + (lane & 3);
            #pragma unroll
            for (int nt = 0; nt < NT; ++nt) {
                int bo = (nt * 8 + (lane >> 2)) * KW + kb;
                uint32_t bh0 = Bw[bo],  bh1 = Bw[bo + 4];
                uint32_t bl0 = BwL[bo], bl1 = BwL[bo + 4];
                mma_bf16(C[nt], ah0, ah1, ah2, ah3, bh0, bh1);
                mma_bf16(C[nt], ah0, ah1, ah2, ah3, bl0, bl1);
                mma_bf16(C[nt], al0, al1, al2, al3, bh0, bh1);
            }
        }
    }

    // ---- epilogue: bias + relu -> position-major global ----
    float* gx = (CONV == 1) ? g_x1 : ((CONV == 2) ? g_x2 : g_x3);
    long long row0 = tb + wid * 16 + (lane >> 2);
    long long row1 = row0 + 8;
    int colb = (lane & 3) * 2;
    #pragma unroll
    for (int nt = 0; nt < NT; ++nt) {
        int col = nt * 8 + colb;
        float b0 = bias[col], b1 = bias[col + 1];
        if (row0 < MTOT) {
            float2 o;
            o.x = fmaxf(C[nt][0] + b0, 0.f);
            o.y = fmaxf(C[nt][1] + b1, 0.f);
            *(float2*)(gx + row0 * N + col) = o;
        }
        if (row1 < MTOT) {
            float2 o;
            o.x = fmaxf(C[nt][2] + b0, 0.f);
            o.y = fmaxf(C[nt][3] + b1, 0.f);
            *(float2*)(gx + row1 * N + col) = o;
        }
    }
}

// ---------------- per-expert MLP ----------------
__global__ void __launch_bounds__(64) mlp_kernel(
    const float* __restrict__ B1,
    const float* __restrict__ W2, const float* __restrict__ B2,
    const float* __restrict__ W3, const float* __restrict__ B3,
    const float* __restrict__ W4, const float* __restrict__ B4,
    const float* __restrict__ W5, const float* __restrict__ B5,
    const float* __restrict__ W6, const float* __restrict__ B6,
    float* __restrict__ out) {
    int e = blockIdx.x;
    int base = blockIdx.y * TB;
    int n = g_cnt[e] - base;
    if (n <= 0) return;
    if (n > TB) n = TB;

    __shared__ float tile[TB * DC];
    __shared__ float hA[TB * 64], hB[TB * 64];
    __shared__ int   sid[TB];
    int j = threadIdx.x;

    if (j < TB) sid[j] = (j < n) ? g_idx[e * NB_MAX + base + j] : -1;
    __syncthreads();

    const float* wrow = g_W1t + (size_t)e * 200704 + (size_t)j * 3136;
    float acc[TB];
    #pragma unroll
    for (int s = 0; s < TB; ++s) acc[s] = 0.f;

    #pragma unroll 1
    for (int dc = 0; dc < 3136; dc += DC) {
        __syncthreads();
        for (int i = j; i < TB * DC; i += 64) {
            int s = i / DC, d = i % DC;
            int bb = sid[s];
            tile[i] = (bb >= 0) ? g_x3[(size_t)bb * C3_OUT + dc + d] : 0.f;
        }
        __syncthreads();
        #pragma unroll 1
        for (int d = 0; d < DC; d += 8) {
            float4 wa = *(const float4*)(wrow + dc + d);
            float4 wb = *(const float4*)(wrow + dc + d + 4);
            #pragma unroll
            for (int s = 0; s < TB; ++s) {
                float4 t1 = *(const float4*)(tile + s * DC + d);
                float4 t2 = *(const float4*)(tile + s * DC + d + 4);
                float a = acc[s];
                a = fmaf(t1.x, wa.x, a); a = fmaf(t1.y, wa.y, a);
                a = fmaf(t1.z, wa.z, a); a = fmaf(t1.w, wa.w, a);
                a = fmaf(t2.x, wb.x, a); a = fmaf(t2.y, wb.y, a);
                a = fmaf(t2.z, wb.z, a); a = fmaf(t2.w, wb.w, a);
                acc[s] = a;
            }
        }
    }
    float b1 = B1[e * 64 + j];
    #pragma unroll
    for (int s = 0; s < TB; ++s) hA[s * 64 + j] = fmaxf(acc[s] + b1, 0.f);
    __syncthreads();

    const float* Ws[4] = {W2, W3, W4, W5};
    const float* Bs[4] = {B2, B3, B4, B5};
    float* hin = hA;
    float* hout = hB;
    #pragma unroll 1
    for (int L = 0; L < 4; ++L) {
        const float* W = Ws[L] + (size_t)e * 4096;
        float bb = Bs[L][e * 64 + j];
        float a2[TB];
        #pragma unroll
        for (int s = 0; s < TB; ++s) a2[s] = bb;
        for (int k = 0; k < 64; ++k) {
            float w = W[k * 64 + j];
            #pragma unroll
            for (int s = 0; s < TB; ++s)
                a2[s] = fmaf(hin[s * 64 + k], w, a2[s]);
        }
        #pragma unroll
        for (int s = 0; s < TB; ++s) hout[s * 64 + j] = fmaxf(a2[s], 0.f);
        __syncthreads();
        float* t = hin; hin = hout; hout = t;
    }

    if (j < NA) {
        const float* W6e = W6 + (size_t)e * 64 * NA;
        float b6 = B6[e * NA + j];
        for (int s = 0; s < n; ++s) {
            float a = b6;
            #pragma unroll
            for (int k = 0; k < 64; ++k)
                a = fmaf(hin[s * 64 + k], W6e[k * NA + j], a);
            out[(size_t)sid[s] * NA + j] = a;
        }
    }
}

// ---------------- launch ----------------
extern "C" void kernel_launch(void* const* d_in, const int* in_sizes, int n_in,
                              void* d_out, int out_size) {
    const float* state = (const float*)d_in[0];
    const int*   rm    = (const int*)d_in[1];
    const float* k1 = (const float*)d_in[2];
    const float* c1 = (const float*)d_in[3];
    const float* k2 = (const float*)d_in[4];
    const float* c2 = (const float*)d_in[5];
    const float* k3 = (const float*)d_in[6];
    const float* c3 = (const float*)d_in[7];
    const float* W1 = (const float*)d_in[8];
    const float* B1 = (const float*)d_in[9];
    const float* W2 = (const float*)d_in[10];
    const float* B2 = (const float*)d_in[11];
    const float* W3 = (const float*)d_in[12];
    const float* B3 = (const float*)d_in[13];
    const float* W4 = (const float*)d_in[14];
    const float* B4 = (const float*)d_in[15];
    const float* W5 = (const float*)d_in[16];
    const float* B5 = (const float*)d_in[17];
    const float* W6 = (const float*)d_in[18];
    const float* B6 = (const float*)d_in[19];
    float* out = (float*)d_out;

    int nB = in_sizes[1];
    if (nB > NB_MAX) nB = NB_MAX;

    const int SM1 = 36864 + 2 * 32 * 400;    //  62464
    const int SM2 = 36864 + 2 * 64 * 1040;   // 169984
    const int SM3 = 36864 + 2 * 64 * 1168;   // 186368
    cudaFuncSetAttribute(conv_mma_kernel<1>, cudaFuncAttributeMaxDynamicSharedMemorySize, SM1);
    cudaFuncSetAttribute(conv_mma_kernel<2>, cudaFuncAttributeMaxDynamicSharedMemorySize, SM2);
    cudaFuncSetAttribute(conv_mma_kernel<3>, cudaFuncAttributeMaxDynamicSharedMemorySize, SM3);

    int M1 = nB * 400, M2 = nB * 81, M3 = nB * 49;

    prep_kernel<<<512, 256>>>(k1, k2, k3, W1);
    assign_kernel<<<1, 256>>>(rm, nB);
    conv_mma_kernel<1><<<(M1 + 127) / 128, 256, SM1>>>(state, c1, M1);
    conv_mma_kernel<2><<<(M2 + 127) / 128, 256, SM2>>>(state, c2, M2);
    conv_mma_kernel<3><<<(M3 + 127) / 128, 256, SM3>>>(state, c3, M3);
    mlp_kernel<<<dim3(NE, (nB + TB - 1) / TB), 64>>>(
        B1, W2, B2, W3, B3, W4, B4, W5, B5, W6, B6, out);
}

// round 8
// speedup vs baseline: 3.2452x; 1.3220x over previous
#include <cuda_runtime.h>
#include <cuda_bf16.h>
#include <cstdint>

// ---------------- problem constants ----------------
#define NB_MAX   2048
#define NE       8
#define NA       6
#define TB       32
#define DC       224           // 3136 = 14*224
#define C3_OUT   3136

// ---------------- scratch (device globals; no allocs allowed) ----------------
// activations, POSITION-MAJOR: [b][pos][channels]
__device__ float g_x1[(size_t)NB_MAX * 400 * 32];
__device__ float g_x2[(size_t)NB_MAX * 81 * 64];
__device__ float g_x3[(size_t)NB_MAX * 49 * 64];
__device__ int   g_cnt[NE];
__device__ int   g_idx[NE * NB_MAX];
// conv weights prepacked as MMA B-fragments: [chunk][k16][col][q] = {bh0,bh1,bl0,bl1}
__device__ uint4 g_B1f[3 * 512];     // N=32: 32*4*4 = 512 uint4/chunk
__device__ uint4 g_B2f[8 * 1024];    // N=64: 1024 uint4/chunk
__device__ uint4 g_B3f[9 * 1024];
// W1 transposed+permuted: [e][j][d'] with d' = p*64 + c  (matches g_x3 pm layout)
__device__ float g_W1t[NE * 64 * 3136];

// ---------------- mma.sync helper ----------------
__device__ __forceinline__ void mma_bf16(float* c, uint32_t a0, uint32_t a1,
                                         uint32_t a2, uint32_t a3,
                                         uint32_t b0, uint32_t b1) {
    asm volatile(
        "mma.sync.aligned.m16n8k16.row.col.f32.bf16.bf16.f32 "
        "{%0,%1,%2,%3}, {%4,%5,%6,%7}, {%8,%9}, {%0,%1,%2,%3};"
        : "+f"(c[0]), "+f"(c[1]), "+f"(c[2]), "+f"(c[3])
        : "r"(a0), "r"(a1), "r"(a2), "r"(a3), "r"(b0), "r"(b1));
}

// ---------------- bf16 hi/lo packing ----------------
__device__ __forceinline__ void packpair(float a, float b, unsigned& h, unsigned& l) {
    __nv_bfloat162 hh = __floats2bfloat162_rn(a, b);
    float ra = a - __bfloat162float(__low2bfloat16(hh));
    float rb = b - __bfloat162float(__high2bfloat16(hh));
    __nv_bfloat162 ll = __floats2bfloat162_rn(ra, rb);
    h = *(unsigned*)&hh; l = *(unsigned*)&ll;
}
__device__ __forceinline__ void pack8(const float* v, uint4& H, uint4& L) {
    unsigned hw[4], lw[4];
    #pragma unroll
    for (int q = 0; q < 4; ++q) packpair(v[2*q], v[2*q+1], hw[q], lw[q]);
    H = make_uint4(hw[0], hw[1], hw[2], hw[3]);
    L = make_uint4(lw[0], lw[1], lw[2], lw[3]);
}
// A tile row = 72 bf16 (144 B); store 8 values at (r, kin0)
__device__ __forceinline__ void store8p(char* pAh, char* pAl, int r, int kin0,
                                        const float* v) {
    int off = r * 144 + kin0 * 2;
    uint4 H, L; pack8(v, H, L);
    *(uint4*)(pAh + off) = H;
    *(uint4*)(pAl + off) = L;
}

// ---------------- weight prepack (fragment layout) + W1 transpose ----------
__global__ void prep_kernel(const float* __restrict__ k1, const float* __restrict__ k2,
                            const float* __restrict__ k3, const float* __restrict__ W1) {
    int t0 = blockIdx.x * blockDim.x + threadIdx.x;
    int stride = gridDim.x * blockDim.x;
    // conv1: N=32, kk = c*64 + kh*8 + kw (natural k1 order)
    for (int t = t0; t < 3 * 512; t += stride) {
        int ch = t / 512, rem = t % 512;
        int k16 = rem >> 7, col = (rem >> 2) & 31, q = rem & 3;
        int kb = ch * 64 + k16 * 16 + 2 * q;
        const float* w = k1 + col * 192;
        uint4 f;
        packpair(w[kb],     w[kb + 1], f.x, f.z);
        packpair(w[kb + 8], w[kb + 9], f.y, f.w);
        g_B1f[t] = f;
    }
    // conv2: kk = tap*32 + c -> k2[j*512 + c*16 + tap]
    for (int t = t0; t < 8 * 1024; t += stride) {
        int ch = t >> 10, rem = t & 1023;
        int k16 = rem >> 8, col = (rem >> 2) & 63, q = rem & 3;
        int kb = ch * 64 + k16 * 16 + 2 * q;
        const float* w = k2 + col * 512;
        auto W2 = [&](int kk) { int tap = kk >> 5, c = kk & 31; return w[c * 16 + tap]; };
        uint4 f;
        packpair(W2(kb),     W2(kb + 1), f.x, f.z);
        packpair(W2(kb + 8), W2(kb + 9), f.y, f.w);
        g_B2f[t] = f;
    }
    // conv3: kk = tap*64 + c -> k3[j*576 + c*9 + tap]
    for (int t = t0; t < 9 * 1024; t += stride) {
        int ch = t >> 10, rem = t & 1023;
        int k16 = rem >> 8, col = (rem >> 2) & 63, q = rem & 3;
        int kb = ch * 64 + k16 * 16 + 2 * q;
        const float* w = k3 + col * 576;
        auto W3 = [&](int kk) { int tap = kk >> 6, c = kk & 63; return w[c * 9 + tap]; };
        uint4 f;
        packpair(W3(kb),     W3(kb + 1), f.x, f.z);
        packpair(W3(kb + 8), W3(kb + 9), f.y, f.w);
        g_B3f[t] = f;
    }
    // W1t: [e][j][d'] with d' = p*64 + c  <->  original d = c*49 + p
    for (int i = t0; i < NE * 64 * 3136; i += stride) {
        int e = i / 200704, rem = i % 200704;
        int j = rem / 3136, dp = rem % 3136;
        int p = dp >> 6, c = dp & 63;
        g_W1t[i] = W1[e * 200704 + (c * 49 + p) * 64 + j];
    }
}

// ---------------- expert bucketing ----------------
__global__ void assign_kernel(const int* __restrict__ rm32, int n) {
    __shared__ int s_is64;
    int tid = threadIdx.x;
    if (tid == 0) s_is64 = 1;
    __syncthreads();
    for (int i = tid; i < 256; i += blockDim.x)
        if (rm32[2*i + 1] != 0) atomicExch(&s_is64, 0);
    if (tid < NE) g_cnt[tid] = 0;
    __syncthreads();
    int is64 = s_is64;
    const long long* rm64 = (const long long*)rm32;
    for (int b = tid; b < n; b += blockDim.x) {
        int e = is64 ? (int)rm64[b] : rm32[b];
        int pos = atomicAdd(&g_cnt[e], 1);
        g_idx[e * NB_MAX + pos] = b;
    }
}

// ---------------- conv-as-GEMM via mma.sync bf16 (hi/lo 3-pass) ------------
// Double-buffered A and per-chunk B; one __syncthreads per chunk.
template<int CONV>
__global__ void __launch_bounds__(256) conv_mma_kernel(
    const float* __restrict__ state, const float* __restrict__ bias, int MTOT) {
    constexpr int KCH = (CONV == 1) ? 3 : ((CONV == 2) ? 8 : 9);
    constexpr int N   = (CONV == 1) ? 32 : 64;
    constexpr int POS = (CONV == 1) ? 400 : ((CONV == 2) ? 81 : 49);
    constexpr int NT  = N / 8;
    constexpr int BCH = N * 16;        // uint4 per B chunk

    extern __shared__ char smem[];
    char* pA  = smem;                           // [2 buf][hi 18432 | lo 18432]
    uint4* pB = (uint4*)(smem + 73728);         // [2 buf][BCH]
    const uint4* gB = (CONV == 1) ? g_B1f : ((CONV == 2) ? g_B2f : g_B3f);

    int tid = threadIdx.x, wid = tid >> 5, lane = tid & 31;
    long long tb = (long long)blockIdx.x * 128;
    int r = tid >> 1, half = tid & 1;
    long long gp = tb + r;
    if (gp >= MTOT) gp = MTOT - 1;
    int b = (int)(gp / POS), p = (int)(gp % POS);

    float C[NT][4];
    #pragma unroll
    for (int nt = 0; nt < NT; ++nt)
        #pragma unroll
        for (int q = 0; q < 4; ++q) C[nt][q] = 0.f;

    int ab0 = (wid * 16 + (lane >> 2)) * 36 + (lane & 3);

    #pragma unroll 1
    for (int ch = 0; ch < KCH; ++ch) {
        char* pAh = pA + (ch & 1) * 36864;
        char* pAl = pAh + 18432;
        uint4* Bs = pB + (ch & 1) * BCH;

        // ---- stage B chunk ----
        for (int i = tid; i < BCH; i += 256) Bs[i] = gB[ch * BCH + i];

        // ---- build A chunk (im2col gather -> bf16 hi/lo) ----
        float v[8];
        if (CONV == 1) {
            int oh = p / 20, ow = p % 20;
            #pragma unroll
            for (int u = 0; u < 4; ++u) {
                int kh = half * 4 + u;
                const float* s = state + ((size_t)(b * 84 + oh * 4 + kh) * 84 + ow * 4) * 3 + ch;
                #pragma unroll
                for (int q = 0; q < 8; ++q) v[q] = s[q * 3];
                store8p(pAh, pAl, r, kh * 8, v);
            }
        } else if (CONV == 2) {
            int oh = p / 9, ow = p % 9;
            int tap = ch * 2 + half, kh = tap >> 2, kw = tap & 3;
            const float* s = g_x1 + ((size_t)b * 400 + (2*oh + kh) * 20 + (2*ow + kw)) * 32;
            #pragma unroll
            for (int u = 0; u < 4; ++u) {
                float4 f0 = ((const float4*)s)[u*2], f1 = ((const float4*)s)[u*2 + 1];
                v[0]=f0.x; v[1]=f0.y; v[2]=f0.z; v[3]=f0.w;
                v[4]=f1.x; v[5]=f1.y; v[6]=f1.z; v[7]=f1.w;
                store8p(pAh, pAl, r, half * 32 + u * 8, v);
            }
        } else {
            int oh = p / 7, ow = p % 7;
            int kh = ch / 3, kw = ch % 3;
            const float* s = g_x2 + ((size_t)b * 81 + (oh + kh) * 9 + (ow + kw)) * 64 + half * 32;
            #pragma unroll
            for (int u = 0; u < 4; ++u) {
                float4 f0 = ((const float4*)s)[u*2], f1 = ((const float4*)s)[u*2 + 1];
                v[0]=f0.x; v[1]=f0.y; v[2]=f0.z; v[3]=f0.w;
                v[4]=f1.x; v[5]=f1.y; v[6]=f1.z; v[7]=f1.w;
                store8p(pAh, pAl, r, half * 32 + u * 8, v);
            }
        }
        __syncthreads();

        // ---- MMA: 4 k16 x NT n-tiles x 3-pass split ----
        uint32_t* Aw  = (uint32_t*)pAh;
        uint32_t* AwL = (uint32_t*)pAl;
        #pragma unroll
        for (int k16 = 0; k16 < 4; ++k16) {
            int ab = ab0 + k16 * 8;
            uint32_t ah0 = Aw[ab],      ah1 = Aw[ab + 288];
            uint32_t ah2 = Aw[ab + 4],  ah3 = Aw[ab + 292];
            uint32_t al0 = AwL[ab],     al1 = AwL[ab + 288];
            uint32_t al2 = AwL[ab + 4], al3 = AwL[ab + 292];
            const uint4* bk = Bs + k16 * N * 4 + (lane >> 2) * 4 + (lane & 3);
            #pragma unroll
            for (int nt = 0; nt < NT; ++nt) {
                uint4 f = bk[nt * 32];
                mma_bf16(C[nt], ah0, ah1, ah2, ah3, f.x, f.y);
                mma_bf16(C[nt], ah0, ah1, ah2, ah3, f.z, f.w);
                mma_bf16(C[nt], al0, al1, al2, al3, f.x, f.y);
            }
        }
    }

    // ---- epilogue: bias + relu -> position-major global ----
    float* gx = (CONV == 1) ? g_x1 : ((CONV == 2) ? g_x2 : g_x3);
    long long row0 = tb + wid * 16 + (lane >> 2);
    long long row1 = row0 + 8;
    int colb = (lane & 3) * 2;
    #pragma unroll
    for (int nt = 0; nt < NT; ++nt) {
        int col = nt * 8 + colb;
        float b0 = bias[col], b1 = bias[col + 1];
        if (row0 < MTOT) {
            float2 o;
            o.x = fmaxf(C[nt][0] + b0, 0.f);
            o.y = fmaxf(C[nt][1] + b1, 0.f);
            *(float2*)(gx + row0 * N + col) = o;
        }
        if (row1 < MTOT) {
            float2 o;
            o.x = fmaxf(C[nt][2] + b0, 0.f);
            o.y = fmaxf(C[nt][3] + b1, 0.f);
            *(float2*)(gx + row1 * N + col) = o;
        }
    }
}

// ---------------- per-expert MLP (128 threads: j x sample-half) ------------
__global__ void __launch_bounds__(128) mlp_kernel(
    const float* __restrict__ B1,
    const float* __restrict__ W2, const float* __restrict__ B2,
    const float* __restrict__ W3, const float* __restrict__ B3,
    const float* __restrict__ W4, const float* __restrict__ B4,
    const float* __restrict__ W5, const float* __restrict__ B5,
    const float* __restrict__ W6, const float* __restrict__ B6,
    float* __restrict__ out) {
    int e = blockIdx.x;
    int base = blockIdx.y * TB;
    int n = g_cnt[e] - base;
    if (n <= 0) return;
    if (n > TB) n = TB;

    __shared__ float tile[TB * DC];
    __shared__ float hA[TB * 64], hB[TB * 64];
    __shared__ int   sid[TB];
    int tid = threadIdx.x, j = tid & 63, sh = tid >> 6;   // sh: sample half
    int s0 = sh * 16;

    if (tid < TB) sid[tid] = (tid < n) ? g_idx[e * NB_MAX + base + tid] : -1;
    __syncthreads();

    const float* wrow = g_W1t + (size_t)e * 200704 + (size_t)j * 3136;
    float acc[16];
    #pragma unroll
    for (int s = 0; s < 16; ++s) acc[s] = 0.f;

    #pragma unroll 1
    for (int dc = 0; dc < 3136; dc += DC) {
        __syncthreads();
        for (int i = tid; i < TB * DC; i += 128) {
            int s = i / DC, d = i % DC;
            int bb = sid[s];
            tile[i] = (bb >= 0) ? g_x3[(size_t)bb * C3_OUT + dc + d] : 0.f;
        }
        __syncthreads();
        #pragma unroll 1
        for (int d = 0; d < DC; d += 8) {
            float4 wa = *(const float4*)(wrow + dc + d);
            float4 wb = *(const float4*)(wrow + dc + d + 4);
            #pragma unroll
            for (int s = 0; s < 16; ++s) {
                const float* tp = tile + (s0 + s) * DC + d;
                float4 t1 = *(const float4*)tp;
                float4 t2 = *(const float4*)(tp + 4);
                float a = acc[s];
                a = fmaf(t1.x, wa.x, a); a = fmaf(t1.y, wa.y, a);
                a = fmaf(t1.z, wa.z, a); a = fmaf(t1.w, wa.w, a);
                a = fmaf(t2.x, wb.x, a); a = fmaf(t2.y, wb.y, a);
                a = fmaf(t2.z, wb.z, a); a = fmaf(t2.w, wb.w, a);
                acc[s] = a;
            }
        }
    }
    float b1 = B1[e * 64 + j];
    #pragma unroll
    for (int s = 0; s < 16; ++s) hA[(s0 + s) * 64 + j] = fmaxf(acc[s] + b1, 0.f);
    __syncthreads();

    const float* Ws[4] = {W2, W3, W4, W5};
    const float* Bs[4] = {B2, B3, B4, B5};
    float* hin = hA;
    float* hout = hB;
    #pragma unroll 1
    for (int L = 0; L < 4; ++L) {
        const float* W = Ws[L] + (size_t)e * 4096;
        float bb = Bs[L][e * 64 + j];
        float a2[16];
        #pragma unroll
        for (int s = 0; s < 16; ++s) a2[s] = bb;
        for (int k = 0; k < 64; ++k) {
            float w = W[k * 64 + j];
            #pragma unroll
            for (int s = 0; s < 16; ++s)
                a2[s] = fmaf(hin[(s0 + s) * 64 + k], w, a2[s]);
        }
        #pragma unroll
        for (int s = 0; s < 16; ++s) hout[(s0 + s) * 64 + j] = fmaxf(a2[s], 0.f);
        __syncthreads();
        float* t = hin; hin = hout; hout = t;
    }

    if (j < NA) {
        const float* W6e = W6 + (size_t)e * 64 * NA;
        float b6 = B6[e * NA + j];
        int send = min(n, s0 + 16);
        for (int s = s0; s < send; ++s) {
            float a = b6;
            #pragma unroll
            for (int k = 0; k < 64; ++k)
                a = fmaf(hin[s * 64 + k], W6e[k * NA + j], a);
            out[(size_t)sid[s] * NA + j] = a;
        }
    }
}

// ---------------- launch ----------------
extern "C" void kernel_launch(void* const* d_in, const int* in_sizes, int n_in,
                              void* d_out, int out_size) {
    const float* state = (const float*)d_in[0];
    const int*   rm    = (const int*)d_in[1];
    const float* k1 = (const float*)d_in[2];
    const float* c1 = (const float*)d_in[3];
    const float* k2 = (const float*)d_in[4];
    const float* c2 = (const float*)d_in[5];
    const float* k3 = (const float*)d_in[6];
    const float* c3 = (const float*)d_in[7];
    const float* W1 = (const float*)d_in[8];
    const float* B1 = (const float*)d_in[9];
    const float* W2 = (const float*)d_in[10];
    const float* B2 = (const float*)d_in[11];
    const float* W3 = (const float*)d_in[12];
    const float* B3 = (const float*)d_in[13];
    const float* W4 = (const float*)d_in[14];
    const float* B4 = (const float*)d_in[15];
    const float* W5 = (const float*)d_in[16];
    const float* B5 = (const float*)d_in[17];
    const float* W6 = (const float*)d_in[18];
    const float* B6 = (const float*)d_in[19];
    float* out = (float*)d_out;

    int nB = in_sizes[1];
    if (nB > NB_MAX) nB = NB_MAX;

    const int SM1 = 73728 + 2 * 512 * 16;    //  90112
    const int SM2 = 73728 + 2 * 1024 * 16;   // 106496
    const int SM3 = SM2;
    cudaFuncSetAttribute(conv_mma_kernel<1>, cudaFuncAttributeMaxDynamicSharedMemorySize, SM1);
    cudaFuncSetAttribute(conv_mma_kernel<2>, cudaFuncAttributeMaxDynamicSharedMemorySize, SM2);
    cudaFuncSetAttribute(conv_mma_kernel<3>, cudaFuncAttributeMaxDynamicSharedMemorySize, SM3);

    int M1 = nB * 400, M2 = nB * 81, M3 = nB * 49;

    prep_kernel<<<512, 256>>>(k1, k2, k3, W1);
    assign_kernel<<<1, 256>>>(rm, nB);
    conv_mma_kernel<1><<<(M1 + 127) / 128, 256, SM1>>>(state, c1, M1);
    conv_mma_kernel<2><<<(M2 + 127) / 128, 256, SM2>>>(state, c2, M2);
    conv_mma_kernel<3><<<(M3 + 127) / 128, 256, SM3>>>(state, c3, M3);
    mlp_kernel<<<dim3(NE, (nB + TB - 1) / TB), 128>>>(
        B1, W2, B2, W3, B3, W4, B4, W5, B5, W6, B6, out);
}

// round 9
// speedup vs baseline: 4.6006x; 1.4177x over previous
#include <cuda_runtime.h>
#include <cuda_bf16.h>
#include <cstdint>

// ---------------- problem constants ----------------
#define NB_MAX   2048
#define NE       8
#define NA       6
#define TB       32
#define DC       224           // 3136 = 14*224
#define C3_OUT   3136

typedef unsigned short ushort_t;

// ---------------- scratch (device globals; no allocs allowed) ----------------
// conv1 input, planar NCHW, bf16 hi/lo split
__device__ ushort_t g_x0h[(size_t)NB_MAX * 3 * 84 * 84];
__device__ ushort_t g_x0l[(size_t)NB_MAX * 3 * 84 * 84];
// activations position-major [b][pos][c], bf16 hi/lo
__device__ ushort_t g_x1h[(size_t)NB_MAX * 400 * 32];
__device__ ushort_t g_x1l[(size_t)NB_MAX * 400 * 32];
__device__ ushort_t g_x2h[(size_t)NB_MAX * 81 * 64];
__device__ ushort_t g_x2l[(size_t)NB_MAX * 81 * 64];
__device__ float    g_x3[(size_t)NB_MAX * 49 * 64];    // fp32 for MLP
__device__ int      g_cnt[NE];
__device__ int      g_idx[NE * NB_MAX];
// conv weights prepacked as MMA B-fragments: [chunk][k16][col][q] = {bh0,bh1,bl0,bl1}
__device__ uint4 g_B1f[3 * 512];
__device__ uint4 g_B2f[8 * 1024];
__device__ uint4 g_B3f[9 * 1024];
// W1 transposed+permuted: [e][j][d'] with d' = p*64 + c
__device__ float g_W1t[NE * 64 * 3136];

// ---------------- mma.sync helper ----------------
__device__ __forceinline__ void mma_bf16(float* c, uint32_t a0, uint32_t a1,
                                         uint32_t a2, uint32_t a3,
                                         uint32_t b0, uint32_t b1) {
    asm volatile(
        "mma.sync.aligned.m16n8k16.row.col.f32.bf16.bf16.f32 "
        "{%0,%1,%2,%3}, {%4,%5,%6,%7}, {%8,%9}, {%0,%1,%2,%3};"
        : "+f"(c[0]), "+f"(c[1]), "+f"(c[2]), "+f"(c[3])
        : "r"(a0), "r"(a1), "r"(a2), "r"(a3), "r"(b0), "r"(b1));
}

// ---------------- bf16 hi/lo packing ----------------
__device__ __forceinline__ void packpair(float a, float b, unsigned& h, unsigned& l) {
    __nv_bfloat162 hh = __floats2bfloat162_rn(a, b);
    float ra = a - __bfloat162float(__low2bfloat16(hh));
    float rb = b - __bfloat162float(__high2bfloat16(hh));
    __nv_bfloat162 ll = __floats2bfloat162_rn(ra, rb);
    h = *(unsigned*)&hh; l = *(unsigned*)&ll;
}
__device__ __forceinline__ uint32_t ld2(const ushort_t* p) {
    return *(const uint32_t*)p;
}

// ---------------- weight prepack + input split + W1 transpose ----------------
__global__ void prep_kernel(const float* __restrict__ state,
                            const float* __restrict__ k1, const float* __restrict__ k2,
                            const float* __restrict__ k3, const float* __restrict__ W1,
                            int nB) {
    int t0 = blockIdx.x * blockDim.x + threadIdx.x;
    int stride = gridDim.x * blockDim.x;
    // conv1 input: NHWC fp32 -> planar NCHW bf16 hi/lo
    int nx0 = nB * 3 * 7056;
    for (int i = t0; i < nx0; i += stride) {
        int b = i / 21168, rem = i % 21168;
        int c = rem / 7056, hw = rem % 7056;
        float v = state[((size_t)b * 7056 + hw) * 3 + c];
        __nv_bfloat16 h = __float2bfloat16_rn(v);
        __nv_bfloat16 l = __float2bfloat16_rn(v - __bfloat162float(h));
        g_x0h[i] = *(ushort_t*)&h;
        g_x0l[i] = *(ushort_t*)&l;
    }
    // conv1 B: kk = c*64 + kh*8 + kw (natural k1 order)
    for (int t = t0; t < 3 * 512; t += stride) {
        int ch = t / 512, rem = t % 512;
        int k16 = rem >> 7, col = (rem >> 2) & 31, q = rem & 3;
        int kb = ch * 64 + k16 * 16 + 2 * q;
        const float* w = k1 + col * 192;
        uint4 f;
        packpair(w[kb],     w[kb + 1], f.x, f.z);
        packpair(w[kb + 8], w[kb + 9], f.y, f.w);
        g_B1f[t] = f;
    }
    // conv2: kk = tap*32 + c -> k2[j*512 + c*16 + tap]
    for (int t = t0; t < 8 * 1024; t += stride) {
        int ch = t >> 10, rem = t & 1023;
        int k16 = rem >> 8, col = (rem >> 2) & 63, q = rem & 3;
        int kb = ch * 64 + k16 * 16 + 2 * q;
        const float* w = k2 + col * 512;
        auto W2f = [&](int kk) { int tap = kk >> 5, c = kk & 31; return w[c * 16 + tap]; };
        uint4 f;
        packpair(W2f(kb),     W2f(kb + 1), f.x, f.z);
        packpair(W2f(kb + 8), W2f(kb + 9), f.y, f.w);
        g_B2f[t] = f;
    }
    // conv3: kk = tap*64 + c -> k3[j*576 + c*9 + tap]
    for (int t = t0; t < 9 * 1024; t += stride) {
        int ch = t >> 10, rem = t & 1023;
        int k16 = rem >> 8, col = (rem >> 2) & 63, q = rem & 3;
        int kb = ch * 64 + k16 * 16 + 2 * q;
        const float* w = k3 + col * 576;
        auto W3f = [&](int kk) { int tap = kk >> 6, c = kk & 63; return w[c * 9 + tap]; };
        uint4 f;
        packpair(W3f(kb),     W3f(kb + 1), f.x, f.z);
        packpair(W3f(kb + 8), W3f(kb + 9), f.y, f.w);
        g_B3f[t] = f;
    }
    // W1t: [e][j][d'] with d' = p*64 + c <-> original d = c*49 + p
    for (int i = t0; i < NE * 64 * 3136; i += stride) {
        int e = i / 200704, rem = i % 200704;
        int j = rem / 3136, dp = rem % 3136;
        int p = dp >> 6, c = dp & 63;
        g_W1t[i] = W1[e * 200704 + (c * 49 + p) * 64 + j];
    }
}

// ---------------- expert bucketing ----------------
__global__ void assign_kernel(const int* __restrict__ rm32, int n) {
    __shared__ int s_is64;
    int tid = threadIdx.x;
    if (tid == 0) s_is64 = 1;
    __syncthreads();
    for (int i = tid; i < 256; i += blockDim.x)
        if (rm32[2*i + 1] != 0) atomicExch(&s_is64, 0);
    if (tid < NE) g_cnt[tid] = 0;
    __syncthreads();
    int is64 = s_is64;
    const long long* rm64 = (const long long*)rm32;
    for (int b = tid; b < n; b += blockDim.x) {
        int e = is64 ? (int)rm64[b] : rm32[b];
        int pos = atomicAdd(&g_cnt[e], 1);
        g_idx[e * NB_MAX + pos] = b;
    }
}

// ---------------- conv-as-GEMM: no smem, no syncs, direct-global fragments --
// Block = 128 threads (4 warps); warp handles 32 rows = 2 m16 tiles.
// CONV=1: 3->32  8x8 s4 (KCH=3, N=32, POS=400)
// CONV=2: 32->64 4x4 s2 (KCH=8, N=64, POS=81)
// CONV=3: 64->64 3x3 s1 (KCH=9, N=64, POS=49)
template<int CONV>
__global__ void __launch_bounds__(128) conv_mma_kernel(
    const float* __restrict__ bias, int MTOT) {
    constexpr int KCH = (CONV == 1) ? 3 : ((CONV == 2) ? 8 : 9);
    constexpr int N   = (CONV == 1) ? 32 : 64;
    constexpr int POS = (CONV == 1) ? 400 : ((CONV == 2) ? 81 : 49);
    constexpr int OW  = (CONV == 1) ? 20 : ((CONV == 2) ? 9 : 7);
    constexpr int NT  = N / 8;
    constexpr int BCH = N * 16;

    const uint4* __restrict__ gB = (CONV == 1) ? g_B1f : ((CONV == 2) ? g_B2f : g_B3f);
    const ushort_t* __restrict__ xh = (CONV == 1) ? g_x0h : ((CONV == 2) ? g_x1h : g_x2h);
    const ushort_t* __restrict__ xl = (CONV == 1) ? g_x0l : ((CONV == 2) ? g_x1l : g_x2l);

    int tid = threadIdx.x, wid = tid >> 5, lane = tid & 31;
    int klo = (lane & 3) * 2;
    long long tb = (long long)blockIdx.x * 128;

    // 4 fragment rows per thread: i = tile*2 + h  (h: row / row+8)
    long long orow[4];
    int pb[4];               // row base (chunk-independent part)
    #pragma unroll
    for (int i = 0; i < 4; ++i) {
        long long gr = tb + wid * 32 + (i >> 1) * 16 + (i & 1) * 8 + (lane >> 2);
        orow[i] = gr;
        if (gr >= MTOT) gr = MTOT - 1;
        int b = (int)(gr / POS), p = (int)(gr % POS);
        int oh = p / OW, ow = p % OW;
        if (CONV == 1)      pb[i] = b * 21168 + oh * 336 + ow * 4;   // + ch*7056 + kh*84 + kw
        else if (CONV == 2) pb[i] = b * 12800 + oh * 1280 + ow * 64; // + kh*640 + kw*32 + c
        else                pb[i] = b * 5184  + oh * 576  + ow * 64; // + kh*576 + kw*64 + c
    }

    float C[2][8][4];
    #pragma unroll
    for (int t = 0; t < 2; ++t)
        #pragma unroll
        for (int nt = 0; nt < NT; ++nt)
            #pragma unroll
            for (int q = 0; q < 4; ++q) C[t][nt][q] = 0.f;

    #pragma unroll 1
    for (int ch = 0; ch < KCH; ++ch) {
        int cb1 = 0, cb2 = 0;        // per-chunk base offsets
        if (CONV == 1)      cb1 = ch * 7056;
        else if (CONV == 3) { int kh = ch / 3, kw = ch % 3; cb1 = kh * 576 + kw * 64; }

        #pragma unroll
        for (int k16 = 0; k16 < 4; ++k16) {
            // per-(k16) address offsets
            int o0, o1;   // offset for a0/a1 (lo k) and a2/a3 (+8)
            if (CONV == 1) {
                o0 = cb1 + (k16 * 2) * 84 + klo;
                o1 = o0 + 84;
            } else if (CONV == 2) {
                int tap = ch * 2 + (k16 >> 1);
                int kh = tap >> 2, kw = tap & 3;
                cb2 = kh * 640 + kw * 32;
                o0 = cb2 + (k16 & 1) * 16 + klo;
                o1 = o0 + 8;
            } else {
                o0 = cb1 + k16 * 16 + klo;
                o1 = o0 + 8;
            }
            uint32_t ah[2][4], al[2][4];
            #pragma unroll
            for (int t = 0; t < 2; ++t) {
                const int r0 = pb[t*2], r1 = pb[t*2 + 1];
                ah[t][0] = ld2(xh + r0 + o0);
                ah[t][1] = ld2(xh + r1 + o0);
                ah[t][2] = ld2(xh + r0 + o1);
                ah[t][3] = ld2(xh + r1 + o1);
                al[t][0] = ld2(xl + r0 + o0);
                al[t][1] = ld2(xl + r1 + o0);
                al[t][2] = ld2(xl + r0 + o1);
                al[t][3] = ld2(xl + r1 + o1);
            }
            const uint4* bk = gB + ch * BCH + k16 * (N * 4) + (lane >> 2) * 4 + (lane & 3);
            #pragma unroll
            for (int nt = 0; nt < NT; ++nt) {
                uint4 f = bk[nt * 32];
                #pragma unroll
                for (int t = 0; t < 2; ++t) {
                    mma_bf16(C[t][nt], ah[t][0], ah[t][1], ah[t][2], ah[t][3], f.x, f.y);
                    mma_bf16(C[t][nt], ah[t][0], ah[t][1], ah[t][2], ah[t][3], f.z, f.w);
                    mma_bf16(C[t][nt], al[t][0], al[t][1], al[t][2], al[t][3], f.x, f.y);
                }
            }
        }
    }

    // ---- epilogue: bias + relu; write bf16 hi/lo (conv1/2) or fp32 (conv3) ----
    #pragma unroll
    for (int t = 0; t < 2; ++t) {
        #pragma unroll
        for (int nt = 0; nt < NT; ++nt) {
            int col = nt * 8 + klo;
            float2 bb = *(const float2*)(bias + col);
            #pragma unroll
            for (int h = 0; h < 2; ++h) {
                long long rw = orow[t*2 + h];
                if (rw >= MTOT) continue;
                float v0 = fmaxf(C[t][nt][h*2]     + bb.x, 0.f);
                float v1 = fmaxf(C[t][nt][h*2 + 1] + bb.y, 0.f);
                if (CONV == 3) {
                    *(float2*)(g_x3 + rw * 64 + col) = make_float2(v0, v1);
                } else {
                    unsigned hh, ll;
                    packpair(v0, v1, hh, ll);
                    if (CONV == 1) {
                        *(uint32_t*)(g_x1h + rw * 32 + col) = hh;
                        *(uint32_t*)(g_x1l + rw * 32 + col) = ll;
                    } else {
                        *(uint32_t*)(g_x2h + rw * 64 + col) = hh;
                        *(uint32_t*)(g_x2l + rw * 64 + col) = ll;
                    }
                }
            }
        }
    }
}

// ---------------- per-expert MLP (256 threads: 64 j x 4 sample-quarters) ----
__global__ void __launch_bounds__(256) mlp_kernel(
    const float* __restrict__ B1,
    const float* __restrict__ W2, const float* __restrict__ B2,
    const float* __restrict__ W3, const float* __restrict__ B3,
    const float* __restrict__ W4, const float* __restrict__ B4,
    const float* __restrict__ W5, const float* __restrict__ B5,
    const float* __restrict__ W6, const float* __restrict__ B6,
    float* __restrict__ out) {
    int e = blockIdx.x;
    int base = blockIdx.y * TB;
    int n = g_cnt[e] - base;
    if (n <= 0) return;
    if (n > TB) n = TB;

    __shared__ float tile[TB * DC];
    __shared__ float hA[TB * 64], hB[TB * 64];
    __shared__ int   sid[TB];
    int tid = threadIdx.x, j = tid & 63, sq = tid >> 6;
    int s0 = sq * 8;

    if (tid < TB) sid[tid] = (tid < n) ? g_idx[e * NB_MAX + base + tid] : -1;
    __syncthreads();

    const float* wrow = g_W1t + (size_t)e * 200704 + (size_t)j * 3136;
    float acc[8];
    #pragma unroll
    for (int s = 0; s < 8; ++s) acc[s] = 0.f;

    #pragma unroll 1
    for (int dc = 0; dc < 3136; dc += DC) {
        __syncthreads();
        for (int i = tid; i < TB * DC; i += 256) {
            int s = i / DC, d = i % DC;
            int bb = sid[s];
            tile[i] = (bb >= 0) ? g_x3[(size_t)bb * C3_OUT + dc + d] : 0.f;
        }
        __syncthreads();
        #pragma unroll 1
        for (int d = 0; d < DC; d += 8) {
            float4 wa = *(const float4*)(wrow + dc + d);
            float4 wb = *(const float4*)(wrow + dc + d + 4);
            #pragma unroll
            for (int s = 0; s < 8; ++s) {
                const float* tp = tile + (s0 + s) * DC + d;
                float4 t1 = *(const float4*)tp;
                float4 t2 = *(const float4*)(tp + 4);
                float a = acc[s];
                a = fmaf(t1.x, wa.x, a); a = fmaf(t1.y, wa.y, a);
                a = fmaf(t1.z, wa.z, a); a = fmaf(t1.w, wa.w, a);
                a = fmaf(t2.x, wb.x, a); a = fmaf(t2.y, wb.y, a);
                a = fmaf(t2.z, wb.z, a); a = fmaf(t2.w, wb.w, a);
                acc[s] = a;
            }
        }
    }
    float b1 = B1[e * 64 + j];
    #pragma unroll
    for (int s = 0; s < 8; ++s) hA[(s0 + s) * 64 + j] = fmaxf(acc[s] + b1, 0.f);
    __syncthreads();

    const float* Ws[4] = {W2, W3, W4, W5};
    const float* Bs[4] = {B2, B3, B4, B5};
    float* hin = hA;
    float* hout = hB;
    #pragma unroll 1
    for (int L = 0; L < 4; ++L) {
        const float* W = Ws[L] + (size_t)e * 4096;
        float bb = Bs[L][e * 64 + j];
        float a2[8];
        #pragma unroll
        for (int s = 0; s < 8; ++s) a2[s] = bb;
        for (int k = 0; k < 64; ++k) {
            float w = W[k * 64 + j];
            #pragma unroll
            for (int s = 0; s < 8; ++s)
                a2[s] = fmaf(hin[(s0 + s) * 64 + k], w, a2[s]);
        }
        #pragma unroll
        for (int s = 0; s < 8; ++s) hout[(s0 + s) * 64 + j] = fmaxf(a2[s], 0.f);
        __syncthreads();
        float* t = hin; hin = hout; hout = t;
    }

    if (j < NA) {
        const float* W6e = W6 + (size_t)e * 64 * NA;
        float b6 = B6[e * NA + j];
        int send = min(n, s0 + 8);
        for (int s = s0; s < send; ++s) {
            float a = b6;
            #pragma unroll
            for (int k = 0; k < 64; ++k)
                a = fmaf(hin[s * 64 + k], W6e[k * NA + j], a);
            out[(size_t)sid[s] * NA + j] = a;
        }
    }
}

// ---------------- launch ----------------
extern "C" void kernel_launch(void* const* d_in, const int* in_sizes, int n_in,
                              void* d_out, int out_size) {
    const float* state = (const float*)d_in[0];
    const int*   rm    = (const int*)d_in[1];
    const float* k1 = (const float*)d_in[2];
    const float* c1 = (const float*)d_in[3];
    const float* k2 = (const float*)d_in[4];
    const float* c2 = (const float*)d_in[5];
    const float* k3 = (const float*)d_in[6];
    const float* c3 = (const float*)d_in[7];
    const float* W1 = (const float*)d_in[8];
    const float* B1 = (const float*)d_in[9];
    const float* W2 = (const float*)d_in[10];
    const float* B2 = (const float*)d_in[11];
    const float* W3 = (const float*)d_in[12];
    const float* B3 = (const float*)d_in[13];
    const float* W4 = (const float*)d_in[14];
    const float* B4 = (const float*)d_in[15];
    const float* W5 = (const float*)d_in[16];
    const float* B5 = (const float*)d_in[17];
    const float* W6 = (const float*)d_in[18];
    const float* B6 = (const float*)d_in[19];
    float* out = (float*)d_out;

    int nB = in_sizes[1];
    if (nB > NB_MAX) nB = NB_MAX;

    int M1 = nB * 400, M2 = nB * 81, M3 = nB * 49;

    prep_kernel<<<1024, 256>>>(state, k1, k2, k3, W1, nB);
    assign_kernel<<<1, 256>>>(rm, nB);
    conv_mma_kernel<1><<<(M1 + 127) / 128, 128>>>(c1, M1);
    conv_mma_kernel<2><<<(M2 + 127) / 128, 128>>>(c2, M2);
    conv_mma_kernel<3><<<(M3 + 127) / 128, 128>>>(c3, M3);
    mlp_kernel<<<dim3(NE, (nB + TB - 1) / TB), 256>>>(
        B1, W2, B2, W3, B3, W4, B4, W5, B5, W6, B6, out);
}